// round 1
// baseline (speedup 1.0000x reference)
#include <cuda_runtime.h>

#define BB 64
#define N1 201
#define DD 128
#define HF 100
#define MM (BB*N1)          // 12864
#define NEGV -1e20f

// ---------------- scratch (device globals: no runtime allocation) ----------------
__device__ __align__(16) float g_hmax[BB*DD];
__device__ __align__(16) float g_gv[BB*DD];
__device__ __align__(16) float g_hhat[MM*DD];                 // 6.6 MB
__device__ __align__(16) float g_proj[16*MM*DD];              // 105 MB: heads 0-3 rmWQ, 4-7 rmWK, 8-11 i1Wk, 12-15 i2Wk
__device__ __align__(16) float g_qvec[16*BB*DD];              // [t*4+h][b][d], t: p1,p2,d1,d2
__device__ __align__(16) float g_rc[MM*32];
__device__ __align__(16) float g_cc[MM*32];
__device__ int   g_a1[BB];
__device__ float g_ll1[BB];
__device__ __align__(16) float g_t2[BB*N1*N1];                // 10.3 MB

// ---------------- K0: per-(b,d) max over N1 ----------------
__global__ void k_hmax(const float* __restrict__ hw) {
    int b = blockIdx.x, d = threadIdx.x;
    const float* p = hw + (size_t)b*N1*DD + d;
    float m = -3.4e38f;
    for (int n = 0; n < N1; n++) m = fmaxf(m, p[n*DD]);
    g_hmax[b*DD + d] = m;
}

// ---------------- K1: g = hmax @ Wg ----------------
__global__ void k_gvec(const float* __restrict__ Wg) {
    __shared__ float hm[DD];
    int b = blockIdx.x, d = threadIdx.x;
    hm[d] = g_hmax[b*DD + d];
    __syncthreads();
    float s = 0.f;
    for (int k = 0; k < DD; k++) s += hm[k] * Wg[k*DD + d];
    g_gv[b*DD + d] = s;
}

// ---------------- K2: h_hat = h_wave @ Wn + g[b] (4 rows per block) ----------------
__global__ void k_hhat(const float* __restrict__ hw, const float* __restrict__ Wn) {
    __shared__ __align__(16) float As[4][DD];
    int r0 = blockIdx.x * 4;
    int d = threadIdx.x;
    #pragma unroll
    for (int rr = 0; rr < 4; rr++) As[rr][d] = hw[(size_t)(r0+rr)*DD + d];
    __syncthreads();
    float s[4];
    #pragma unroll
    for (int rr = 0; rr < 4; rr++) s[rr] = g_gv[((r0+rr)/N1)*DD + d];
    for (int k = 0; k < DD; k++) {
        float w = Wn[k*DD + d];
        #pragma unroll
        for (int rr = 0; rr < 4; rr++) s[rr] += As[rr][k] * w;
    }
    #pragma unroll
    for (int rr = 0; rr < 4; rr++) g_hhat[(size_t)(r0+rr)*DD + d] = s[rr];
}

// ---------------- K3: big projection GEMM [12864,128] x [128, 16*128] ----------------
// block tile 64x64, BK=16, 256 threads, 4x4 per thread. One head per block column.
__global__ __launch_bounds__(256) void k_gemm(const float* __restrict__ wa,
                                              const float* __restrict__ wb,
                                              const float* __restrict__ wc,
                                              const float* __restrict__ wd) {
    __shared__ __align__(16) float As[16][64];
    __shared__ __align__(16) float Bs[16][64];
    const float* A = g_hhat;
    int bm = blockIdx.x;              // 0..200
    int bn = blockIdx.y;              // 0..31
    int h16 = bn >> 1;
    int d0  = (bn & 1) * 64;
    const float* wsel;
    switch (h16 >> 2) { case 0: wsel = wa; break; case 1: wsel = wb; break;
                        case 2: wsel = wc; break; default: wsel = wd; }
    const float* W = wsel + (size_t)(h16 & 3) * DD * DD;

    int tid = threadIdx.x;
    int tx = tid & 15, ty = tid >> 4;
    float c[4][4] = {};
    int arow = tid >> 2,  ac0 = (tid & 3) * 4;
    int brow = tid >> 4,  bc0 = (tid & 15) * 4;
    const float* Ap = A + (size_t)(bm*64 + arow) * DD;

    for (int k0 = 0; k0 < DD; k0 += 16) {
        float4 a4 = *(const float4*)(Ap + k0 + ac0);
        As[ac0+0][arow] = a4.x; As[ac0+1][arow] = a4.y;
        As[ac0+2][arow] = a4.z; As[ac0+3][arow] = a4.w;
        *(float4*)&Bs[brow][bc0] = *(const float4*)(W + (size_t)(k0+brow)*DD + d0 + bc0);
        __syncthreads();
        #pragma unroll
        for (int kk = 0; kk < 16; kk++) {
            float4 av = *(float4*)&As[kk][ty*4];
            float4 bv = *(float4*)&Bs[kk][tx*4];
            c[0][0] += av.x*bv.x; c[0][1] += av.x*bv.y; c[0][2] += av.x*bv.z; c[0][3] += av.x*bv.w;
            c[1][0] += av.y*bv.x; c[1][1] += av.y*bv.y; c[1][2] += av.y*bv.z; c[1][3] += av.y*bv.w;
            c[2][0] += av.z*bv.x; c[2][1] += av.z*bv.y; c[2][2] += av.z*bv.z; c[2][3] += av.z*bv.w;
            c[3][0] += av.w*bv.x; c[3][1] += av.w*bv.y; c[3][2] += av.w*bv.z; c[3][3] += av.w*bv.w;
        }
        __syncthreads();
    }
    float* out = g_proj + (size_t)h16 * MM * DD;
    int row0 = bm*64 + ty*4, col0 = d0 + tx*4;
    #pragma unroll
    for (int i2 = 0; i2 < 4; i2++) {
        float4 v; v.x = c[i2][0]; v.y = c[i2][1]; v.z = c[i2][2]; v.w = c[i2][3];
        *(float4*)(out + (size_t)(row0+i2)*DD + col0) = v;
    }
}

// ---------------- K4: removal compat + MLP + t1 softmax/argmax ----------------
__global__ void k_t1(const int* __restrict__ sol_g, const float* __restrict__ selrec,
                     const int* __restrict__ pre_action,
                     const float* __restrict__ w1, const float* __restrict__ b1,
                     const float* __restrict__ w2, const float* __restrict__ b2,
                     const float* __restrict__ w3, const float* __restrict__ b3) {
    __shared__ int sol[N1], inv[N1];
    __shared__ float t1s[HF];
    __shared__ float W1[12*32], B1[32], W2[32*32], B2[32], W3[32];
    int b = blockIdx.x, tid = threadIdx.x;
    for (int i = tid; i < N1; i += 128) sol[i] = sol_g[b*N1 + i];
    for (int i = tid; i < 12*32; i += 128) W1[i] = w1[i];
    for (int i = tid; i < 32*32; i += 128) W2[i] = w2[i];
    if (tid < 32) { B1[tid] = b1[tid]; B2[tid] = b2[tid]; W3[tid] = w3[tid]; }
    __syncthreads();
    for (int i = tid; i < N1; i += 128) inv[sol[i]] = i;
    __syncthreads();

    if (tid < HF) {
        int m = tid;
        float feat[12];
        #pragma unroll
        for (int half = 0; half < 2; half++) {
            int n = m + 1 + half*HF;
            int ipre  = inv[n];
            int ipost = sol[sol[n]];
            #pragma unroll
            for (int h = 0; h < 4; h++) {
                const float* Qpre  = g_proj + ((size_t)h     *MM + b*N1 + ipre )*DD;
                const float* Qn    = g_proj + ((size_t)h     *MM + b*N1 + n    )*DD;
                const float* Kn    = g_proj + ((size_t)(4+h) *MM + b*N1 + n    )*DD;
                const float* Kpost = g_proj + ((size_t)(4+h) *MM + b*N1 + ipost)*DD;
                float s1 = 0.f, s2 = 0.f, s3 = 0.f;
                for (int d4 = 0; d4 < DD; d4 += 4) {
                    float4 qp = *(const float4*)(Qpre + d4);
                    float4 qn = *(const float4*)(Qn + d4);
                    float4 kn = *(const float4*)(Kn + d4);
                    float4 kp = *(const float4*)(Kpost + d4);
                    s1 += qp.x*kn.x + qp.y*kn.y + qp.z*kn.z + qp.w*kn.w;
                    s2 += qn.x*kp.x + qn.y*kp.y + qn.z*kp.z + qn.w*kp.w;
                    s3 += qp.x*kp.x + qp.y*kp.y + qp.z*kp.z + qp.w*kp.w;
                }
                feat[half*4 + h] = s1 + s2 - s3;
            }
        }
        #pragma unroll
        for (int s = 0; s < 4; s++) feat[8+s] = selrec[b*4*HF + s*HF + m];

        float h1[32];
        #pragma unroll
        for (int c = 0; c < 32; c++) {
            float s = B1[c];
            #pragma unroll
            for (int f = 0; f < 12; f++) s += feat[f] * W1[f*32 + c];
            h1[c] = fmaxf(s, 0.f);
        }
        float h2[32];
        #pragma unroll
        for (int c = 0; c < 32; c++) {
            float s = B2[c];
            #pragma unroll
            for (int f = 0; f < 32; f++) s += h1[f] * W2[f*32 + c];
            h2[c] = fmaxf(s, 0.f);
        }
        float o = b3[0];
        #pragma unroll
        for (int c = 0; c < 32; c++) o += h2[c] * W3[c];
        float t1 = tanhf(o) * 6.0f;
        if (pre_action[0] > 0 && m == pre_action[b*2]) t1 = NEGV;
        t1s[m] = t1;
    }
    __syncthreads();
    if (tid == 0) {
        float mx = t1s[0]; int am = 0;
        for (int m = 1; m < HF; m++) if (t1s[m] > mx) { mx = t1s[m]; am = m; }
        float se = 0.f;
        for (int m = 0; m < HF; m++) se += expf(t1s[m] - mx);
        g_a1[b] = am;
        g_ll1[b] = -logf(se);
    }
}

// ---------------- K5: q-side projections of h_p / h_d ----------------
__global__ void k_qvec(const float* __restrict__ i1wq, const float* __restrict__ i2wq) {
    __shared__ float hp[DD];
    int x = blockIdx.x;               // t*4+h
    int t = x >> 2, h = x & 3;
    int b = blockIdx.y;
    int d = threadIdx.x;
    int a1 = g_a1[b];
    int pos = (t < 2) ? (1 + a1) : (1 + HF + a1);
    hp[d] = g_hhat[(size_t)(b*N1 + pos)*DD + d];
    __syncthreads();
    const float* W = ((t & 1) ? i2wq : i1wq) + (size_t)h*DD*DD;
    float s = 0.f;
    for (int k = 0; k < DD; k++) s += hp[k] * W[k*DD + d];
    g_qvec[((size_t)x*BB + b)*DD + d] = s;
}

// ---------------- K6: row/col layer-1 contributions ----------------
__global__ void k_rccc(const int* __restrict__ sol_g,
                       const float* __restrict__ w1, const float* __restrict__ b1v) {
    __shared__ float qv[16*DD];
    __shared__ float W1[16*32], B1[32];
    int b = blockIdx.y;
    int tid = threadIdx.x;
    int i = blockIdx.x * 128 + tid;
    for (int l = tid; l < 16*DD; l += 128) {
        int x = l / DD, d = l % DD;
        qv[l] = g_qvec[((size_t)x*BB + b)*DD + d];
    }
    for (int l = tid; l < 16*32; l += 128) W1[l] = w1[l];
    if (tid < 32) B1[tid] = b1v[tid];
    __syncthreads();
    if (i < N1) {
        const float invs = 0.08838834764831845f;  // 1/sqrt(128)
        float r8[8], c8[8];
        int si = sol_g[b*N1 + i];
        #pragma unroll
        for (int h = 0; h < 4; h++) {
            const float* K1 = g_proj + ((size_t)(8+h) *MM + b*N1 + i )*DD;
            const float* K2 = g_proj + ((size_t)(12+h)*MM + b*N1 + si)*DD;
            const float* qp1 = qv + (0*4 + h)*DD;
            const float* qp2 = qv + (1*4 + h)*DD;
            const float* qd1 = qv + (2*4 + h)*DD;
            const float* qd2 = qv + (3*4 + h)*DD;
            float sp1 = 0.f, sd1 = 0.f, sp2 = 0.f, sd2 = 0.f;
            for (int d = 0; d < DD; d++) {
                float k1 = K1[d], k2 = K2[d];
                sp1 += qp1[d]*k1; sd1 += qd1[d]*k1;
                sp2 += qp2[d]*k2; sd2 += qd2[d]*k2;
            }
            r8[h]   = sp1*invs;  c8[h]   = sd1*invs;
            r8[4+h] = sp2*invs;  c8[4+h] = sd2*invs;
        }
        #pragma unroll
        for (int c = 0; c < 32; c++) {
            float rs = 0.f, cs = B1[c];
            #pragma unroll
            for (int f = 0; f < 8; f++) {
                rs += r8[f] * W1[f*32 + c];
                cs += c8[f] * W1[(8+f)*32 + c];
            }
            g_rc[(size_t)(b*N1 + i)*32 + c] = rs;
            g_cc[(size_t)(b*N1 + i)*32 + c] = cs;
        }
    }
}

// ---------------- K7: fused reinsertion MLP over [B,N1,N1] (dominant) ----------------
#define ITILE 3
__global__ __launch_bounds__(224) void k_t2(const unsigned char* __restrict__ maskt,
                                            const float* __restrict__ w2, const float* __restrict__ b2,
                                            const float* __restrict__ w3, const float* __restrict__ b3) {
    __shared__ __align__(16) float W2[32*32];
    __shared__ float B2[32], W3[32], rcs[ITILE][32];
    __shared__ float B3;
    int b = blockIdx.y;
    int i0 = blockIdx.x * ITILE;      // 67*3 = 201 exactly
    int tid = threadIdx.x;
    for (int l = tid; l < 1024; l += 224) W2[l] = w2[l];
    if (tid < 32) { B2[tid] = b2[tid]; W3[tid] = w3[tid]; }
    if (tid == 0) B3 = b3[0];
    for (int l = tid; l < ITILE*32; l += 224) {
        int it = l >> 5, c = l & 31;
        rcs[it][c] = g_rc[(size_t)(b*N1 + i0 + it)*32 + c];
    }
    __syncthreads();

    int j = tid;
    if (j < N1) {
        float cj[32];
        const float4* ccp = (const float4*)(g_cc + (size_t)(b*N1 + j)*32);
        #pragma unroll
        for (int q = 0; q < 8; q++) {
            float4 v = ccp[q];
            cj[q*4] = v.x; cj[q*4+1] = v.y; cj[q*4+2] = v.z; cj[q*4+3] = v.w;
        }
        #pragma unroll
        for (int it = 0; it < ITILE; it++) {
            int i = i0 + it;
            float acc[32];
            #pragma unroll
            for (int c = 0; c < 32; c++) acc[c] = B2[c];
            #pragma unroll
            for (int kk = 0; kk < 32; kk++) {
                float h1 = fmaxf(rcs[it][kk] + cj[kk], 0.f);
                const float4* wrow = (const float4*)(W2 + kk*32);
                #pragma unroll
                for (int q = 0; q < 8; q++) {
                    float4 w = wrow[q];
                    acc[q*4+0] += h1*w.x; acc[q*4+1] += h1*w.y;
                    acc[q*4+2] += h1*w.z; acc[q*4+3] += h1*w.w;
                }
            }
            float o = B3;
            #pragma unroll
            for (int c = 0; c < 32; c++) o += fmaxf(acc[c], 0.f) * W3[c];
            float t2v = maskt[((size_t)b*N1 + i)*N1 + j] ? NEGV : tanhf(o)*6.0f;
            g_t2[(size_t)b*N1*N1 + i*N1 + j] = t2v;
        }
    }
}

// ---------------- K8: per-batch argmax + logsumexp over 40401, write outputs ----------------
__global__ void k_red(float* __restrict__ out) {
    __shared__ float smax[512];
    __shared__ int   sidx[512];
    __shared__ float ssum[512];
    int b = blockIdx.x, tid = threadIdx.x;
    const float* t2 = g_t2 + (size_t)b*N1*N1;
    float mx = -3.4e38f; int am = 0x7fffffff;
    for (int idx = tid; idx < N1*N1; idx += 512) {
        float v = t2[idx];
        if (v > mx || (v == mx && idx < am)) { mx = v; am = idx; }
    }
    smax[tid] = mx; sidx[tid] = am;
    __syncthreads();
    for (int s = 256; s > 0; s >>= 1) {
        if (tid < s) {
            float v2 = smax[tid+s]; int i2 = sidx[tid+s];
            if (v2 > smax[tid] || (v2 == smax[tid] && i2 < sidx[tid])) {
                smax[tid] = v2; sidx[tid] = i2;
            }
        }
        __syncthreads();
    }
    float gmax = smax[0]; int gidx = sidx[0];
    float se = 0.f;
    for (int idx = tid; idx < N1*N1; idx += 512) se += expf(t2[idx] - gmax);
    ssum[tid] = se;
    __syncthreads();
    for (int s = 256; s > 0; s >>= 1) {
        if (tid < s) ssum[tid] += ssum[tid+s];
        __syncthreads();
    }
    if (tid == 0) {
        float ll2 = -logf(ssum[0]);
        int a1 = g_a1[b];
        out[b*3 + 0] = (float)a1;
        out[b*3 + 1] = (float)(gidx / N1);
        out[b*3 + 2] = (float)(gidx % N1);
        out[BB*3 + b] = g_ll1[b] + ll2;
    }
}

// ---------------- launch ----------------
extern "C" void kernel_launch(void* const* d_in, const int* in_sizes, int n_in,
                              void* d_out, int out_size) {
    const float* h_wave      = (const float*)d_in[0];
    const int*   solution    = (const int*)d_in[1];
    const float* selrec      = (const float*)d_in[2];
    const int*   pre_action  = (const int*)d_in[3];
    const unsigned char* mt  = (const unsigned char*)d_in[4];
    const float* Wn  = (const float*)d_in[5];
    const float* Wg  = (const float*)d_in[6];
    const float* rmWQ = (const float*)d_in[7];
    const float* rmWK = (const float*)d_in[8];
    const float* rw1 = (const float*)d_in[9];
    const float* rb1 = (const float*)d_in[10];
    const float* rw2 = (const float*)d_in[11];
    const float* rb2 = (const float*)d_in[12];
    const float* rw3 = (const float*)d_in[13];
    const float* rb3 = (const float*)d_in[14];
    const float* i1q = (const float*)d_in[15];
    const float* i1k = (const float*)d_in[16];
    const float* i2q = (const float*)d_in[17];
    const float* i2k = (const float*)d_in[18];
    const float* ew1 = (const float*)d_in[19];
    const float* eb1 = (const float*)d_in[20];
    const float* ew2 = (const float*)d_in[21];
    const float* eb2 = (const float*)d_in[22];
    const float* ew3 = (const float*)d_in[23];
    const float* eb3 = (const float*)d_in[24];
    float* out = (float*)d_out;

    k_hmax<<<BB, DD>>>(h_wave);
    k_gvec<<<BB, DD>>>(Wg);
    k_hhat<<<MM/4, DD>>>(h_wave, Wn);
    {
        dim3 gg(201, 32);
        k_gemm<<<gg, 256>>>(rmWQ, rmWK, i1k, i2k);
    }
    k_t1<<<BB, 128>>>(solution, selrec, pre_action, rw1, rb1, rw2, rb2, rw3, rb3);
    {
        dim3 gq(16, BB);
        k_qvec<<<gq, DD>>>(i1q, i2q);
    }
    {
        dim3 gr(2, BB);
        k_rccc<<<gr, 128>>>(solution, ew1, eb1);
    }
    {
        dim3 gt(67, BB);
        k_t2<<<gt, 224>>>(mt, ew2, eb2, ew3, eb3);
    }
    k_red<<<BB, 512>>>(out);
}

// round 3
// speedup vs baseline: 2.2810x; 2.2810x over previous
#include <cuda_runtime.h>

#define BB 64
#define N1 201
#define DD 128
#define HF 100
#define MM (BB*N1)          // 12864
#define NEGV -1e20f
#define NT2 67              // t2 blocks per batch (67*3 = 201)

typedef unsigned long long ull;

// ---------------- scratch ----------------
__device__ __align__(16) float g_gv[BB*DD];
__device__ __align__(16) float g_hhat[MM*DD];        // 6.6 MB
__device__ __align__(16) float g_M[4*DD*DD];         // WQ_h @ WK_h^T (removal)
__device__ __align__(16) float g_proj[4*MM*DD];      // P = hhat @ M_h (26 MB)
__device__ __align__(16) float g_qt[16*BB*DD];       // folded qtilde vectors
__device__ __align__(16) float g_rc[MM*32];
__device__ __align__(16) float g_cc[MM*32];
__device__ int   g_a1[BB];
__device__ float g_ll1[BB];
__device__ ull   g_pkey[BB*NT2];
__device__ float g_psum[BB*NT2];

// ---------------- f32x2 helpers ----------------
__device__ __forceinline__ ull ffma2(ull a, ull b, ull c) {
    ull d;
    asm("fma.rn.f32x2 %0, %1, %2, %3;" : "=l"(d) : "l"(a), "l"(b), "l"(c));
    return d;
}
__device__ __forceinline__ ull pack2(float x) {
    ull r;
    asm("mov.b64 %0, {%1, %2};" : "=l"(r) : "f"(x), "f"(x));
    return r;
}
__device__ __forceinline__ void unpack2(ull v, float& lo, float& hi) {
    asm("mov.b64 {%0, %1}, %2;" : "=f"(lo), "=f"(hi) : "l"(v));
}

// ---------------- K1: hmax + g = hmax @ Wg ----------------
__global__ void k_prep(const float* __restrict__ hw, const float* __restrict__ Wg) {
    __shared__ float hm[DD];
    int b = blockIdx.x, d = threadIdx.x;
    const float* p = hw + (size_t)b*N1*DD + d;
    float m = -3.4e38f;
    for (int n = 0; n < N1; n++) m = fmaxf(m, p[n*DD]);
    hm[d] = m;
    __syncthreads();
    float s = 0.f;
    for (int k = 0; k < DD; k++) s += hm[k] * Wg[k*DD + d];
    g_gv[b*DD + d] = s;
}

// ---------------- K2: h_hat = h_wave @ Wn + g[b] ----------------
__global__ void k_hhat(const float* __restrict__ hw, const float* __restrict__ Wn) {
    __shared__ __align__(16) float As[8][DD];
    int r0 = blockIdx.x * 8;
    int d = threadIdx.x;
    #pragma unroll
    for (int rr = 0; rr < 8; rr++) As[rr][d] = hw[(size_t)(r0+rr)*DD + d];
    __syncthreads();
    float s[8];
    #pragma unroll
    for (int rr = 0; rr < 8; rr++) s[rr] = g_gv[((r0+rr)/N1)*DD + d];
    for (int k = 0; k < DD; k++) {
        float w = Wn[k*DD + d];
        #pragma unroll
        for (int rr = 0; rr < 8; rr++) s[rr] += As[rr][k] * w;
    }
    #pragma unroll
    for (int rr = 0; rr < 8; rr++) g_hhat[(size_t)(r0+rr)*DD + d] = s[rr];
}

// ---------------- K3: M_h = rmWQ_h @ rmWK_h^T (tiny) ----------------
__global__ void k_mmat(const float* __restrict__ WQ, const float* __restrict__ WK) {
    __shared__ float wk[DD];
    int h = blockIdx.x, dp = blockIdx.y;
    int tid = threadIdx.x;
    wk[tid] = WK[(size_t)(h*DD + dp)*DD + tid];
    __syncthreads();
    const float4* q4 = (const float4*)(WQ + (size_t)(h*DD + tid)*DD);
    const float4* k4 = (const float4*)wk;
    float s = 0.f;
    #pragma unroll
    for (int c = 0; c < 32; c++) {
        float4 a = q4[c], bq = k4[c];
        s += a.x*bq.x + a.y*bq.y + a.z*bq.z + a.w*bq.w;
    }
    g_M[(size_t)(h*DD + tid)*DD + dp] = s;
}

// ---------------- K4: P = hhat @ M (4 heads) — f32x2 GEMM ----------------
__global__ __launch_bounds__(256) void k_pgemm() {
    __shared__ __align__(16) float As[16][64];
    __shared__ __align__(16) float Bs[16][64];
    const float* A = g_hhat;
    int bm = blockIdx.x;              // 0..200
    int bn = blockIdx.y;              // 0..7
    int h  = bn >> 1;
    int d0 = (bn & 1) * 64;
    const float* W = g_M + (size_t)h * DD * DD;

    int tid = threadIdx.x;
    int tx = tid & 15, ty = tid >> 4;
    ull c2[2][4] = {};
    int arow = tid >> 2,  ac0 = (tid & 3) * 4;
    int brow = tid >> 4,  bc0 = (tid & 15) * 4;
    const float* Ap = A + (size_t)(bm*64 + arow) * DD;

    for (int k0 = 0; k0 < DD; k0 += 16) {
        float4 a4 = *(const float4*)(Ap + k0 + ac0);
        As[ac0+0][arow] = a4.x; As[ac0+1][arow] = a4.y;
        As[ac0+2][arow] = a4.z; As[ac0+3][arow] = a4.w;
        *(float4*)&Bs[brow][bc0] = *(const float4*)(W + (size_t)(k0+brow)*DD + d0 + bc0);
        __syncthreads();
        #pragma unroll
        for (int kk = 0; kk < 16; kk++) {
            const ull* ap = (const ull*)&As[kk][ty*4];
            ull a01 = ap[0], a23 = ap[1];
            float4 bv = *(float4*)&Bs[kk][tx*4];
            ull bb0 = pack2(bv.x), bb1 = pack2(bv.y);
            ull bb2 = pack2(bv.z), bb3 = pack2(bv.w);
            c2[0][0] = ffma2(a01, bb0, c2[0][0]);
            c2[0][1] = ffma2(a01, bb1, c2[0][1]);
            c2[0][2] = ffma2(a01, bb2, c2[0][2]);
            c2[0][3] = ffma2(a01, bb3, c2[0][3]);
            c2[1][0] = ffma2(a23, bb0, c2[1][0]);
            c2[1][1] = ffma2(a23, bb1, c2[1][1]);
            c2[1][2] = ffma2(a23, bb2, c2[1][2]);
            c2[1][3] = ffma2(a23, bb3, c2[1][3]);
        }
        __syncthreads();
    }
    float* out = g_proj + (size_t)h * MM * DD;
    int row0 = bm*64 + ty*4, col0 = d0 + tx*4;
    #pragma unroll
    for (int mp = 0; mp < 2; mp++) {
        float l0,h0,l1,h1,l2,h2,l3,h3;
        unpack2(c2[mp][0], l0, h0); unpack2(c2[mp][1], l1, h1);
        unpack2(c2[mp][2], l2, h2); unpack2(c2[mp][3], l3, h3);
        float4 v0; v0.x=l0; v0.y=l1; v0.z=l2; v0.w=l3;
        float4 v1; v1.x=h0; v1.y=h1; v1.z=h2; v1.w=h3;
        *(float4*)(out + (size_t)(row0 + mp*2 + 0)*DD + col0) = v0;
        *(float4*)(out + (size_t)(row0 + mp*2 + 1)*DD + col0) = v1;
    }
}

// ---------------- K5: removal — warp-cooperative compat + MLP + softmax/argmax ----------------
__global__ __launch_bounds__(256) void k_t1(const int* __restrict__ sol_g,
                     const float* __restrict__ selrec,
                     const int* __restrict__ pre_action,
                     const float* __restrict__ w1, const float* __restrict__ b1,
                     const float* __restrict__ w2, const float* __restrict__ b2,
                     const float* __restrict__ w3, const float* __restrict__ b3) {
    __shared__ int sol[N1], inv[N1];
    __shared__ float feat_sh[HF][13];
    __shared__ float t1s[HF];
    __shared__ float W1[12*32], B1[32], W2s[32*32], B2s[32], W3s[32];
    int b = blockIdx.x, tid = threadIdx.x;
    int wid = tid >> 5, lane = tid & 31;
    for (int i = tid; i < N1; i += 256) sol[i] = sol_g[b*N1 + i];
    for (int i = tid; i < 12*32; i += 256) W1[i] = w1[i];
    for (int i = tid; i < 32*32; i += 256) W2s[i] = w2[i];
    if (tid < 32) { B1[tid] = b1[tid]; B2s[tid] = b2[tid]; W3s[tid] = w3[tid]; }
    __syncthreads();
    for (int i = tid; i < N1; i += 256) inv[sol[i]] = i;
    __syncthreads();

    for (int item = wid; item < 200; item += 8) {
        int n = item + 1;
        int half = (item < HF) ? 0 : 1;
        int m = (item < HF) ? item : (item - HF);
        int ipre  = inv[n];
        int ipost = sol[sol[n]];
        float4 xn = ((const float4*)(g_hhat + (size_t)(b*N1 + n    )*DD))[lane];
        float4 xp = ((const float4*)(g_hhat + (size_t)(b*N1 + ipost)*DD))[lane];
        #pragma unroll
        for (int h = 0; h < 4; h++) {
            float4 pp = ((const float4*)(g_proj + ((size_t)h*MM + b*N1 + ipre)*DD))[lane];
            float4 pn = ((const float4*)(g_proj + ((size_t)h*MM + b*N1 + n   )*DD))[lane];
            float s = pp.x*xn.x + pp.y*xn.y + pp.z*xn.z + pp.w*xn.w
                    + pn.x*xp.x + pn.y*xp.y + pn.z*xp.z + pn.w*xp.w
                    - (pp.x*xp.x + pp.y*xp.y + pp.z*xp.z + pp.w*xp.w);
            #pragma unroll
            for (int off = 16; off > 0; off >>= 1) s += __shfl_xor_sync(0xFFFFFFFF, s, off);
            if (lane == 0) feat_sh[m][half*4 + h] = s;
        }
    }
    for (int l = tid; l < 4*HF; l += 256) {
        int s = l / HF, m = l % HF;
        feat_sh[m][8 + s] = selrec[b*4*HF + l];
    }
    __syncthreads();

    if (tid < HF) {
        int m = tid;
        float h1[32];
        #pragma unroll
        for (int c = 0; c < 32; c++) {
            float s = B1[c];
            #pragma unroll
            for (int f = 0; f < 12; f++) s += feat_sh[m][f] * W1[f*32 + c];
            h1[c] = fmaxf(s, 0.f);
        }
        float h2[32];
        #pragma unroll
        for (int c = 0; c < 32; c++) {
            float s = B2s[c];
            #pragma unroll
            for (int f = 0; f < 32; f++) s += h1[f] * W2s[f*32 + c];
            h2[c] = fmaxf(s, 0.f);
        }
        float o = b3[0];
        #pragma unroll
        for (int c = 0; c < 32; c++) o += h2[c] * W3s[c];
        float t1 = tanhf(o) * 6.0f;
        if (pre_action[0] > 0 && m == pre_action[b*2]) t1 = NEGV;
        t1s[m] = t1;
    }
    __syncthreads();
    if (tid == 0) {
        float mx = t1s[0]; int am = 0;
        for (int m = 1; m < HF; m++) if (t1s[m] > mx) { mx = t1s[m]; am = m; }
        float se = 0.f;
        for (int m = 0; m < HF; m++) se += expf(t1s[m] - mx);
        g_a1[b] = am;
        g_ll1[b] = -logf(se);
    }
}

// ---------------- K6: qtilde = Wk @ (Wq^T h_sel) (16 per batch) ----------------
__global__ void k_qt(const float* __restrict__ i1q, const float* __restrict__ i1k,
                     const float* __restrict__ i2q, const float* __restrict__ i2k) {
    __shared__ float hp[DD];
    __shared__ float u[DD];
    __shared__ float Ws[DD*33];
    int x = blockIdx.x;               // t*4+h
    int t = x >> 2, h = x & 3;
    int b = blockIdx.y;
    int tid = threadIdx.x;
    int a1 = g_a1[b];
    int pos = (t < 2) ? (1 + a1) : (1 + HF + a1);
    hp[tid] = g_hhat[(size_t)(b*N1 + pos)*DD + tid];
    __syncthreads();
    const float* Wq = ((t & 1) ? i2q : i1q) + (size_t)h*DD*DD;
    const float* Wk = ((t & 1) ? i2k : i1k) + (size_t)h*DD*DD;
    float su = 0.f;
    for (int k = 0; k < DD; k++) su += hp[k] * Wq[k*DD + tid];
    u[tid] = su;
    __syncthreads();
    float acc = 0.f;
    for (int e0 = 0; e0 < DD; e0 += 32) {
        for (int l = tid; l < DD*32; l += 128) {
            int dd = l >> 5, ee = l & 31;
            Ws[dd*33 + ee] = Wk[(size_t)dd*DD + e0 + ee];
        }
        __syncthreads();
        const float* wr = Ws + tid*33;
        #pragma unroll
        for (int ee = 0; ee < 32; ee++) acc += u[e0+ee] * wr[ee];
        __syncthreads();
    }
    g_qt[((size_t)x*BB + b)*DD + tid] = acc;
}

// ---------------- K7: row/col layer-1 contributions ----------------
__global__ void k_rc(const int* __restrict__ sol_g,
                     const float* __restrict__ w1, const float* __restrict__ b1v) {
    __shared__ __align__(16) float qv[16*DD];
    __shared__ float W1[16*32], B1[32];
    int b = blockIdx.y;
    int tid = threadIdx.x;
    int i = blockIdx.x * 128 + tid;
    for (int l = tid; l < 16*DD; l += 128) {
        int x = l >> 7, d = l & 127;
        qv[l] = g_qt[((size_t)x*BB + b)*DD + d];
    }
    for (int l = tid; l < 16*32; l += 128) W1[l] = w1[l];
    if (tid < 32) B1[tid] = b1v[tid];
    __syncthreads();
    if (i < N1) {
        const float invs = 0.08838834764831845f;  // 1/sqrt(128)
        int si = sol_g[b*N1 + i];
        const float4* hi4 = (const float4*)(g_hhat + (size_t)(b*N1 + i )*DD);
        const float4* hs4 = (const float4*)(g_hhat + (size_t)(b*N1 + si)*DD);
        float s[16] = {};
        for (int c = 0; c < 32; c++) {
            float4 xi = hi4[c], xs = hs4[c];
            #pragma unroll
            for (int h = 0; h < 4; h++) {
                float4 q0 = ((const float4*)(qv + (0*4+h)*DD))[c];
                float4 q1 = ((const float4*)(qv + (1*4+h)*DD))[c];
                float4 q2 = ((const float4*)(qv + (2*4+h)*DD))[c];
                float4 q3 = ((const float4*)(qv + (3*4+h)*DD))[c];
                s[h]    += q0.x*xi.x + q0.y*xi.y + q0.z*xi.z + q0.w*xi.w;
                s[4+h]  += q1.x*xs.x + q1.y*xs.y + q1.z*xs.z + q1.w*xs.w;
                s[8+h]  += q2.x*xi.x + q2.y*xi.y + q2.z*xi.z + q2.w*xi.w;
                s[12+h] += q3.x*xs.x + q3.y*xs.y + q3.z*xs.z + q3.w*xs.w;
            }
        }
        #pragma unroll
        for (int c = 0; c < 32; c++) {
            float rs = 0.f, cs = B1[c];
            #pragma unroll
            for (int f = 0; f < 8; f++) {
                rs += s[f]*invs       * W1[f*32 + c];
                cs += s[8+f]*invs     * W1[(8+f)*32 + c];
            }
            g_rc[(size_t)(b*N1 + i)*32 + c] = rs;
            g_cc[(size_t)(b*N1 + i)*32 + c] = cs;
        }
    }
}

// ---------------- K8: fused reinsertion MLP + in-block reduction — f32x2 ----------------
#define ITILE 3
__global__ __launch_bounds__(256) void k_t2(const unsigned char* __restrict__ maskt,
                                            const float* __restrict__ w2, const float* __restrict__ b2,
                                            const float* __restrict__ w3, const float* __restrict__ b3) {
    __shared__ __align__(16) float W2[32*32];
    __shared__ __align__(8)  float B2[32];
    __shared__ float W3[32], rcs[ITILE][32];
    __shared__ float cjs[N1*33];
    __shared__ ull   sk[256];
    __shared__ float ss[256];
    __shared__ float B3;
    int b = blockIdx.y;
    int i0 = blockIdx.x * ITILE;
    int tid = threadIdx.x;
    for (int l = tid; l < 1024; l += 256) W2[l] = w2[l];
    if (tid < 32) { B2[tid] = b2[tid]; W3[tid] = w3[tid]; }
    if (tid == 0) B3 = b3[0];
    if (tid < ITILE*32) {
        int it = tid >> 5, c = tid & 31;
        rcs[it][c] = g_rc[(size_t)(b*N1 + i0 + it)*32 + c];
    }
    for (int l = tid; l < N1*32; l += 256) {
        int j = l >> 5, c = l & 31;
        cjs[j*33 + c] = g_cc[(size_t)(b*N1 + j)*32 + c];
    }
    __syncthreads();

    ull bk = 0; float bs = 0.f;
    int j = tid;
    if (j < N1) {
        const ull* B2d = (const ull*)B2;
        const float* cj = cjs + j*33;
        #pragma unroll
        for (int it = 0; it < ITILE; it++) {
            int i = i0 + it;
            ull acc2[16];
            #pragma unroll
            for (int q = 0; q < 16; q++) acc2[q] = B2d[q];
            #pragma unroll
            for (int kk = 0; kk < 32; kk++) {
                float h1 = fmaxf(rcs[it][kk] + cj[kk], 0.f);
                ull hh = pack2(h1);
                const ull* wrow = (const ull*)(W2 + kk*32);
                #pragma unroll
                for (int q = 0; q < 16; q++) acc2[q] = ffma2(hh, wrow[q], acc2[q]);
            }
            float o = B3;
            #pragma unroll
            for (int q = 0; q < 16; q++) {
                float lo, hi;
                unpack2(acc2[q], lo, hi);
                o += fmaxf(lo, 0.f) * W3[2*q] + fmaxf(hi, 0.f) * W3[2*q+1];
            }
            float t2v = maskt[((size_t)b*N1 + i)*N1 + j] ? NEGV : tanhf(o)*6.0f;
            unsigned int lin = (unsigned int)(i*N1 + j);
            unsigned int u = __float_as_uint(t2v);
            unsigned int ord = (u >> 31) ? ~u : (u | 0x80000000u);
            ull key = ((ull)ord << 32) | (0xFFFFFFFFu - lin);
            if (key > bk) bk = key;
            bs += expf(t2v - 6.f);
        }
    }
    sk[tid] = bk; ss[tid] = bs;
    __syncthreads();
    for (int s = 128; s > 0; s >>= 1) {
        if (tid < s) {
            if (sk[tid+s] > sk[tid]) sk[tid] = sk[tid+s];
            ss[tid] += ss[tid+s];
        }
        __syncthreads();
    }
    if (tid == 0) {
        g_pkey[b*NT2 + blockIdx.x] = sk[0];
        g_psum[b*NT2 + blockIdx.x] = ss[0];
    }
}

// ---------------- K9: final per-batch reduce (deterministic) ----------------
__global__ void k_red(float* __restrict__ out) {
    int b = threadIdx.x;
    if (b < BB) {
        ull bk = 0; float s = 0.f;
        for (int p = 0; p < NT2; p++) {
            ull k = g_pkey[b*NT2 + p];
            if (k > bk) bk = k;
            s += g_psum[b*NT2 + p];
        }
        unsigned int ord = (unsigned int)(bk >> 32);
        unsigned int u = (ord & 0x80000000u) ? (ord ^ 0x80000000u) : ~ord;
        float vmax = __uint_as_float(u);
        unsigned int lin = 0xFFFFFFFFu - (unsigned int)(bk & 0xFFFFFFFFu);
        float ll2 = vmax - 6.f - logf(s);
        out[b*3 + 0] = (float)g_a1[b];
        out[b*3 + 1] = (float)(lin / N1);
        out[b*3 + 2] = (float)(lin % N1);
        out[BB*3 + b] = g_ll1[b] + ll2;
    }
}

// ---------------- launch ----------------
extern "C" void kernel_launch(void* const* d_in, const int* in_sizes, int n_in,
                              void* d_out, int out_size) {
    const float* h_wave      = (const float*)d_in[0];
    const int*   solution    = (const int*)d_in[1];
    const float* selrec      = (const float*)d_in[2];
    const int*   pre_action  = (const int*)d_in[3];
    const unsigned char* mt  = (const unsigned char*)d_in[4];
    const float* Wn  = (const float*)d_in[5];
    const float* Wg  = (const float*)d_in[6];
    const float* rmWQ = (const float*)d_in[7];
    const float* rmWK = (const float*)d_in[8];
    const float* rw1 = (const float*)d_in[9];
    const float* rb1 = (const float*)d_in[10];
    const float* rw2 = (const float*)d_in[11];
    const float* rb2 = (const float*)d_in[12];
    const float* rw3 = (const float*)d_in[13];
    const float* rb3 = (const float*)d_in[14];
    const float* i1q = (const float*)d_in[15];
    const float* i1k = (const float*)d_in[16];
    const float* i2q = (const float*)d_in[17];
    const float* i2k = (const float*)d_in[18];
    const float* ew1 = (const float*)d_in[19];
    const float* eb1 = (const float*)d_in[20];
    const float* ew2 = (const float*)d_in[21];
    const float* eb2 = (const float*)d_in[22];
    const float* ew3 = (const float*)d_in[23];
    const float* eb3 = (const float*)d_in[24];
    float* out = (float*)d_out;

    k_prep<<<BB, DD>>>(h_wave, Wg);
    k_hhat<<<MM/8, DD>>>(h_wave, Wn);
    {
        dim3 gm(4, 128);
        k_mmat<<<gm, DD>>>(rmWQ, rmWK);
    }
    {
        dim3 gg(201, 8);
        k_pgemm<<<gg, 256>>>();
    }
    k_t1<<<BB, 256>>>(solution, selrec, pre_action, rw1, rb1, rw2, rb2, rw3, rb3);
    {
        dim3 gq(16, BB);
        k_qt<<<gq, 128>>>(i1q, i1k, i2q, i2k);
    }
    {
        dim3 gr(2, BB);
        k_rc<<<gr, 128>>>(solution, ew1, eb1);
    }
    {
        dim3 gt(NT2, BB);
        k_t2<<<gt, 256>>>(mt, ew2, eb2, ew3, eb3);
    }
    k_red<<<1, 64>>>(out);
}

// round 4
// speedup vs baseline: 15.8252x; 6.9380x over previous
#include <cuda_runtime.h>

#define BB 64
#define N1 201
#define DD 128
#define HF 100
#define MM (BB*N1)          // 12864
#define NEGV -1e20f
#define NT2B 101            // t2 blocks per batch (ceil(201/2))

typedef unsigned long long ull;

// ---------------- scratch ----------------
__device__ __align__(16) float g_gv[BB*DD];
__device__ __align__(16) float g_hhat[MM*DD];        // 6.6 MB
__device__ __align__(16) float g_M[4*DD*DD];         // WQ_h @ WK_h^T (removal)
__device__ __align__(16) float g_proj[4*MM*DD];      // P = hhat @ M_h (26 MB)
__device__ __align__(16) float g_qt[16*BB*DD];       // folded qtilde vectors
__device__ __align__(16) float g_rc[MM*32];
__device__ __align__(16) float g_cc[MM*32];
__device__ int   g_a1[BB];
__device__ float g_ll1[BB];
__device__ ull   g_pkey[BB*NT2B];
__device__ float g_psum[BB*NT2B];

// ---------------- f32x2 helpers ----------------
__device__ __forceinline__ ull ffma2(ull a, ull b, ull c) {
    ull d;
    asm("fma.rn.f32x2 %0, %1, %2, %3;" : "=l"(d) : "l"(a), "l"(b), "l"(c));
    return d;
}
__device__ __forceinline__ ull pack2(float x) {
    ull r;
    asm("mov.b64 %0, {%1, %2};" : "=l"(r) : "f"(x), "f"(x));
    return r;
}
__device__ __forceinline__ void unpack2(ull v, float& lo, float& hi) {
    asm("mov.b64 {%0, %1}, %2;" : "=f"(lo), "=f"(hi) : "l"(v));
}

// ---------------- K1: hmax + g = hmax @ Wg ----------------
__global__ void k_prep(const float* __restrict__ hw, const float* __restrict__ Wg) {
    __shared__ float hm[DD];
    int b = blockIdx.x, d = threadIdx.x;
    const float* p = hw + (size_t)b*N1*DD + d;
    float m = -3.4e38f;
    for (int n = 0; n < N1; n++) m = fmaxf(m, p[n*DD]);
    hm[d] = m;
    __syncthreads();
    float s = 0.f;
    for (int k = 0; k < DD; k++) s += hm[k] * Wg[k*DD + d];
    g_gv[b*DD + d] = s;
}

// ---------------- K2: h_hat = h_wave @ Wn + g[b] ----------------
__global__ void k_hhat(const float* __restrict__ hw, const float* __restrict__ Wn) {
    __shared__ __align__(16) float As[8][DD];
    int r0 = blockIdx.x * 8;
    int d = threadIdx.x;
    #pragma unroll
    for (int rr = 0; rr < 8; rr++) As[rr][d] = hw[(size_t)(r0+rr)*DD + d];
    __syncthreads();
    float s[8];
    #pragma unroll
    for (int rr = 0; rr < 8; rr++) s[rr] = g_gv[((r0+rr)/N1)*DD + d];
    for (int k = 0; k < DD; k++) {
        float w = Wn[k*DD + d];
        #pragma unroll
        for (int rr = 0; rr < 8; rr++) s[rr] += As[rr][k] * w;
    }
    #pragma unroll
    for (int rr = 0; rr < 8; rr++) g_hhat[(size_t)(r0+rr)*DD + d] = s[rr];
}

// ---------------- K3: M_h = rmWQ_h @ rmWK_h^T (tiny) ----------------
__global__ void k_mmat(const float* __restrict__ WQ, const float* __restrict__ WK) {
    __shared__ float wk[DD];
    int h = blockIdx.x, dp = blockIdx.y;
    int tid = threadIdx.x;
    wk[tid] = WK[(size_t)(h*DD + dp)*DD + tid];
    __syncthreads();
    const float4* q4 = (const float4*)(WQ + (size_t)(h*DD + tid)*DD);
    const float4* k4 = (const float4*)wk;
    float s = 0.f;
    #pragma unroll
    for (int c = 0; c < 32; c++) {
        float4 a = q4[c], bq = k4[c];
        s += a.x*bq.x + a.y*bq.y + a.z*bq.z + a.w*bq.w;
    }
    g_M[(size_t)(h*DD + tid)*DD + dp] = s;
}

// ---------------- K4: P = hhat @ M (4 heads) — f32x2 GEMM, 8x4 per thread ----------------
__global__ __launch_bounds__(128, 1) void k_pgemm() {
    __shared__ __align__(16) float As[16][64];
    __shared__ __align__(16) float Bs[16][64];
    int bm = blockIdx.x;              // 0..200
    int bn = blockIdx.y;              // 0..7
    int h  = bn >> 1;
    int d0 = (bn & 1) * 64;
    const float* W = g_M + (size_t)h * DD * DD;

    int tid = threadIdx.x;
    int tx = tid & 15, ty = tid >> 4;              // tx: n-group, ty: m-group (0..7)
    int arow = tid >> 1, ac0 = (tid & 1) * 8;
    int brow = tid >> 3, bc0 = (tid & 7) * 8;
    const float* Ap = g_hhat + (size_t)(bm*64 + arow) * DD;
    ull c2[4][4] = {};

    for (int k0 = 0; k0 < DD; k0 += 16) {
        float4 a0 = *(const float4*)(Ap + k0 + ac0);
        float4 a1 = *(const float4*)(Ap + k0 + ac0 + 4);
        As[ac0+0][arow] = a0.x; As[ac0+1][arow] = a0.y;
        As[ac0+2][arow] = a0.z; As[ac0+3][arow] = a0.w;
        As[ac0+4][arow] = a1.x; As[ac0+5][arow] = a1.y;
        As[ac0+6][arow] = a1.z; As[ac0+7][arow] = a1.w;
        *(float4*)&Bs[brow][bc0]   = *(const float4*)(W + (size_t)(k0+brow)*DD + d0 + bc0);
        *(float4*)&Bs[brow][bc0+4] = *(const float4*)(W + (size_t)(k0+brow)*DD + d0 + bc0 + 4);
        __syncthreads();
        #pragma unroll
        for (int kk = 0; kk < 16; kk++) {
            const ull* ap = (const ull*)&As[kk][ty*8];
            ull a01 = ap[0], a23 = ap[1], a45 = ap[2], a67 = ap[3];
            float4 bv = *(const float4*)&Bs[kk][tx*4];
            ull b0 = pack2(bv.x), b1 = pack2(bv.y), b2 = pack2(bv.z), b3 = pack2(bv.w);
            c2[0][0]=ffma2(a01,b0,c2[0][0]); c2[0][1]=ffma2(a01,b1,c2[0][1]);
            c2[0][2]=ffma2(a01,b2,c2[0][2]); c2[0][3]=ffma2(a01,b3,c2[0][3]);
            c2[1][0]=ffma2(a23,b0,c2[1][0]); c2[1][1]=ffma2(a23,b1,c2[1][1]);
            c2[1][2]=ffma2(a23,b2,c2[1][2]); c2[1][3]=ffma2(a23,b3,c2[1][3]);
            c2[2][0]=ffma2(a45,b0,c2[2][0]); c2[2][1]=ffma2(a45,b1,c2[2][1]);
            c2[2][2]=ffma2(a45,b2,c2[2][2]); c2[2][3]=ffma2(a45,b3,c2[2][3]);
            c2[3][0]=ffma2(a67,b0,c2[3][0]); c2[3][1]=ffma2(a67,b1,c2[3][1]);
            c2[3][2]=ffma2(a67,b2,c2[3][2]); c2[3][3]=ffma2(a67,b3,c2[3][3]);
        }
        __syncthreads();
    }
    float* out = g_proj + (size_t)h * MM * DD;
    int row0 = bm*64 + ty*8, col0 = d0 + tx*4;
    #pragma unroll
    for (int p = 0; p < 4; p++) {
        float l0,h0,l1,h1,l2,h2,l3,h3;
        unpack2(c2[p][0], l0, h0); unpack2(c2[p][1], l1, h1);
        unpack2(c2[p][2], l2, h2); unpack2(c2[p][3], l3, h3);
        float4 v0; v0.x=l0; v0.y=l1; v0.z=l2; v0.w=l3;
        float4 v1; v1.x=h0; v1.y=h1; v1.z=h2; v1.w=h3;
        *(float4*)(out + (size_t)(row0 + 2*p + 0)*DD + col0) = v0;
        *(float4*)(out + (size_t)(row0 + 2*p + 1)*DD + col0) = v1;
    }
}

// ---------------- K5: removal — warp-cooperative compat + MLP + softmax/argmax ----------------
__global__ __launch_bounds__(256) void k_t1(const int* __restrict__ sol_g,
                     const float* __restrict__ selrec,
                     const int* __restrict__ pre_action,
                     const float* __restrict__ w1, const float* __restrict__ b1,
                     const float* __restrict__ w2, const float* __restrict__ b2,
                     const float* __restrict__ w3, const float* __restrict__ b3) {
    __shared__ int sol[N1], inv[N1];
    __shared__ float feat_sh[HF][13];
    __shared__ float t1s[HF];
    __shared__ float W1[12*32], B1[32], W2s[32*32], B2s[32], W3s[32];
    int b = blockIdx.x, tid = threadIdx.x;
    int wid = tid >> 5, lane = tid & 31;
    for (int i = tid; i < N1; i += 256) sol[i] = sol_g[b*N1 + i];
    for (int i = tid; i < 12*32; i += 256) W1[i] = w1[i];
    for (int i = tid; i < 32*32; i += 256) W2s[i] = w2[i];
    if (tid < 32) { B1[tid] = b1[tid]; B2s[tid] = b2[tid]; W3s[tid] = w3[tid]; }
    __syncthreads();
    for (int i = tid; i < N1; i += 256) inv[sol[i]] = i;
    __syncthreads();

    for (int item = wid; item < 200; item += 8) {
        int n = item + 1;
        int half = (item < HF) ? 0 : 1;
        int m = (item < HF) ? item : (item - HF);
        int ipre  = inv[n];
        int ipost = sol[sol[n]];
        float4 xn = ((const float4*)(g_hhat + (size_t)(b*N1 + n    )*DD))[lane];
        float4 xp = ((const float4*)(g_hhat + (size_t)(b*N1 + ipost)*DD))[lane];
        #pragma unroll
        for (int h = 0; h < 4; h++) {
            float4 pp = ((const float4*)(g_proj + ((size_t)h*MM + b*N1 + ipre)*DD))[lane];
            float4 pn = ((const float4*)(g_proj + ((size_t)h*MM + b*N1 + n   )*DD))[lane];
            float s = pp.x*xn.x + pp.y*xn.y + pp.z*xn.z + pp.w*xn.w
                    + pn.x*xp.x + pn.y*xp.y + pn.z*xp.z + pn.w*xp.w
                    - (pp.x*xp.x + pp.y*xp.y + pp.z*xp.z + pp.w*xp.w);
            #pragma unroll
            for (int off = 16; off > 0; off >>= 1) s += __shfl_xor_sync(0xFFFFFFFF, s, off);
            if (lane == 0) feat_sh[m][half*4 + h] = s;
        }
    }
    for (int l = tid; l < 4*HF; l += 256) {
        int s = l / HF, m = l % HF;
        feat_sh[m][8 + s] = selrec[b*4*HF + l];
    }
    __syncthreads();

    if (tid < HF) {
        int m = tid;
        float h1[32];
        #pragma unroll
        for (int c = 0; c < 32; c++) {
            float s = B1[c];
            #pragma unroll
            for (int f = 0; f < 12; f++) s += feat_sh[m][f] * W1[f*32 + c];
            h1[c] = fmaxf(s, 0.f);
        }
        float h2[32];
        #pragma unroll
        for (int c = 0; c < 32; c++) {
            float s = B2s[c];
            #pragma unroll
            for (int f = 0; f < 32; f++) s += h1[f] * W2s[f*32 + c];
            h2[c] = fmaxf(s, 0.f);
        }
        float o = b3[0];
        #pragma unroll
        for (int c = 0; c < 32; c++) o += h2[c] * W3s[c];
        float t1 = tanhf(o) * 6.0f;
        if (pre_action[0] > 0 && m == pre_action[b*2]) t1 = NEGV;
        t1s[m] = t1;
    }
    __syncthreads();
    if (tid == 0) {
        float mx = t1s[0]; int am = 0;
        for (int m = 1; m < HF; m++) if (t1s[m] > mx) { mx = t1s[m]; am = m; }
        float se = 0.f;
        for (int m = 0; m < HF; m++) se += expf(t1s[m] - mx);
        g_a1[b] = am;
        g_ll1[b] = -logf(se);
    }
}

// ---------------- K6: qtilde = Wk @ (Wq^T h_sel) (16 per batch) ----------------
__global__ void k_qt(const float* __restrict__ i1q, const float* __restrict__ i1k,
                     const float* __restrict__ i2q, const float* __restrict__ i2k) {
    __shared__ float hp[DD];
    __shared__ float u[DD];
    __shared__ float Ws[DD*33];
    int x = blockIdx.x;               // t*4+h
    int t = x >> 2, h = x & 3;
    int b = blockIdx.y;
    int tid = threadIdx.x;
    int a1 = g_a1[b];
    int pos = (t < 2) ? (1 + a1) : (1 + HF + a1);
    hp[tid] = g_hhat[(size_t)(b*N1 + pos)*DD + tid];
    __syncthreads();
    const float* Wq = ((t & 1) ? i2q : i1q) + (size_t)h*DD*DD;
    const float* Wk = ((t & 1) ? i2k : i1k) + (size_t)h*DD*DD;
    float su = 0.f;
    for (int k = 0; k < DD; k++) su += hp[k] * Wq[k*DD + tid];
    u[tid] = su;
    __syncthreads();
    float acc = 0.f;
    for (int e0 = 0; e0 < DD; e0 += 32) {
        for (int l = tid; l < DD*32; l += 128) {
            int dd = l >> 5, ee = l & 31;
            Ws[dd*33 + ee] = Wk[(size_t)dd*DD + e0 + ee];
        }
        __syncthreads();
        const float* wr = Ws + tid*33;
        #pragma unroll
        for (int ee = 0; ee < 32; ee++) acc += u[e0+ee] * wr[ee];
        __syncthreads();
    }
    g_qt[((size_t)x*BB + b)*DD + tid] = acc;
}

// ---------------- K7: row/col layer-1 contributions ----------------
__global__ void k_rc(const int* __restrict__ sol_g,
                     const float* __restrict__ w1, const float* __restrict__ b1v) {
    __shared__ __align__(16) float qv[16*DD];
    __shared__ float W1[16*32], B1[32];
    int b = blockIdx.y;
    int tid = threadIdx.x;
    int i = blockIdx.x * 128 + tid;
    for (int l = tid; l < 16*DD; l += 128) {
        int x = l >> 7, d = l & 127;
        qv[l] = g_qt[((size_t)x*BB + b)*DD + d];
    }
    for (int l = tid; l < 16*32; l += 128) W1[l] = w1[l];
    if (tid < 32) B1[tid] = b1v[tid];
    __syncthreads();
    if (i < N1) {
        const float invs = 0.08838834764831845f;  // 1/sqrt(128)
        int si = sol_g[b*N1 + i];
        const float4* hi4 = (const float4*)(g_hhat + (size_t)(b*N1 + i )*DD);
        const float4* hs4 = (const float4*)(g_hhat + (size_t)(b*N1 + si)*DD);
        float s[16] = {};
        for (int c = 0; c < 32; c++) {
            float4 xi = hi4[c], xs = hs4[c];
            #pragma unroll
            for (int h = 0; h < 4; h++) {
                float4 q0 = ((const float4*)(qv + (0*4+h)*DD))[c];
                float4 q1 = ((const float4*)(qv + (1*4+h)*DD))[c];
                float4 q2 = ((const float4*)(qv + (2*4+h)*DD))[c];
                float4 q3 = ((const float4*)(qv + (3*4+h)*DD))[c];
                s[h]    += q0.x*xi.x + q0.y*xi.y + q0.z*xi.z + q0.w*xi.w;
                s[4+h]  += q1.x*xs.x + q1.y*xs.y + q1.z*xs.z + q1.w*xs.w;
                s[8+h]  += q2.x*xi.x + q2.y*xi.y + q2.z*xi.z + q2.w*xi.w;
                s[12+h] += q3.x*xs.x + q3.y*xs.y + q3.z*xs.z + q3.w*xs.w;
            }
        }
        #pragma unroll
        for (int c = 0; c < 32; c++) {
            float rs = 0.f, cs = B1[c];
            #pragma unroll
            for (int f = 0; f < 8; f++) {
                rs += s[f]*invs   * W1[f*32 + c];
                cs += s[8+f]*invs * W1[(8+f)*32 + c];
            }
            g_rc[(size_t)(b*N1 + i)*32 + c] = rs;
            g_cc[(size_t)(b*N1 + i)*32 + c] = cs;
        }
    }
}

// ---------------- K8: fused reinsertion MLP + in-block reduction — f32x2, kk-outer ----------------
__global__ __launch_bounds__(256, 1) void k_t2(const unsigned char* __restrict__ maskt,
                                               const float* __restrict__ w2, const float* __restrict__ b2,
                                               const float* __restrict__ w3, const float* __restrict__ b3) {
    __shared__ __align__(16) float W2[32*32];
    __shared__ __align__(8)  float B2[32];
    __shared__ float W3[32];
    __shared__ float rc0[32], rc1[32];
    __shared__ float cjs[N1*33];
    __shared__ ull   skw[8];
    __shared__ float ssw[8];
    __shared__ float B3;
    int b = blockIdx.y;
    int i0 = blockIdx.x * 2;
    int tid = threadIdx.x;
    int wid = tid >> 5, lane = tid & 31;
    for (int l = tid; l < 1024; l += 256) W2[l] = w2[l];
    if (tid < 32) { B2[tid] = b2[tid]; W3[tid] = w3[tid]; }
    if (tid == 0) B3 = b3[0];
    if (tid < 32)      rc0[tid]    = g_rc[(size_t)(b*N1 + i0)*32 + tid];
    else if (tid < 64) rc1[tid-32] = (i0+1 < N1) ? g_rc[(size_t)(b*N1 + i0 + 1)*32 + (tid-32)] : 0.f;
    for (int l = tid; l < N1*32; l += 256) {
        int j = l >> 5, c = l & 31;
        cjs[j*33 + c] = g_cc[(size_t)(b*N1 + j)*32 + c];
    }
    __syncthreads();

    ull bk = 0; float bs = 0.f;
    int j = tid;
    if (j < N1) {
        const ull* B2d = (const ull*)B2;
        const float* cj = cjs + j*33;
        ull acc0[16], acc1[16];
        #pragma unroll
        for (int q = 0; q < 16; q++) { acc0[q] = B2d[q]; acc1[q] = B2d[q]; }
        #pragma unroll 4
        for (int kk = 0; kk < 32; kk++) {
            float cjk = cj[kk];
            ull hh0 = pack2(fmaxf(rc0[kk] + cjk, 0.f));
            ull hh1 = pack2(fmaxf(rc1[kk] + cjk, 0.f));
            const ull* wrow = (const ull*)(W2 + kk*32);
            #pragma unroll
            for (int q = 0; q < 16; q++) {
                ull w = wrow[q];
                acc0[q] = ffma2(hh0, w, acc0[q]);
                acc1[q] = ffma2(hh1, w, acc1[q]);
            }
        }
        #pragma unroll
        for (int it = 0; it < 2; it++) {
            int i = i0 + it;
            if (i < N1) {
                float o = B3;
                #pragma unroll
                for (int q = 0; q < 16; q++) {
                    float lo, hi;
                    unpack2(it == 0 ? acc0[q] : acc1[q], lo, hi);
                    o += fmaxf(lo, 0.f) * W3[2*q] + fmaxf(hi, 0.f) * W3[2*q+1];
                }
                float t2v = maskt[((size_t)b*N1 + i)*N1 + j] ? NEGV : tanhf(o)*6.0f;
                unsigned int lin = (unsigned int)(i*N1 + j);
                unsigned int u = __float_as_uint(t2v);
                unsigned int ord = (u >> 31) ? ~u : (u | 0x80000000u);
                ull key = ((ull)ord << 32) | (0xFFFFFFFFu - lin);
                if (key > bk) bk = key;
                bs += expf(t2v - 6.f);
            }
        }
    }
    #pragma unroll
    for (int off = 16; off > 0; off >>= 1) {
        ull ok = __shfl_xor_sync(0xFFFFFFFF, bk, off);
        float os = __shfl_xor_sync(0xFFFFFFFF, bs, off);
        if (ok > bk) bk = ok;
        bs += os;
    }
    if (lane == 0) { skw[wid] = bk; ssw[wid] = bs; }
    __syncthreads();
    if (tid == 0) {
        ull k = skw[0]; float s = ssw[0];
        #pragma unroll
        for (int w = 1; w < 8; w++) {
            if (skw[w] > k) k = skw[w];
            s += ssw[w];
        }
        g_pkey[b*NT2B + blockIdx.x] = k;
        g_psum[b*NT2B + blockIdx.x] = s;
    }
}

// ---------------- K9: final per-batch reduce (deterministic) ----------------
__global__ void k_red(float* __restrict__ out) {
    int b = threadIdx.x;
    if (b < BB) {
        ull bk = 0; float s = 0.f;
        for (int p = 0; p < NT2B; p++) {
            ull k = g_pkey[b*NT2B + p];
            if (k > bk) bk = k;
            s += g_psum[b*NT2B + p];
        }
        unsigned int ord = (unsigned int)(bk >> 32);
        unsigned int u = (ord & 0x80000000u) ? (ord ^ 0x80000000u) : ~ord;
        float vmax = __uint_as_float(u);
        unsigned int lin = 0xFFFFFFFFu - (unsigned int)(bk & 0xFFFFFFFFu);
        float ll2 = vmax - 6.f - logf(s);
        out[b*3 + 0] = (float)g_a1[b];
        out[b*3 + 1] = (float)(lin / N1);
        out[b*3 + 2] = (float)(lin % N1);
        out[BB*3 + b] = g_ll1[b] + ll2;
    }
}

// ---------------- launch ----------------
extern "C" void kernel_launch(void* const* d_in, const int* in_sizes, int n_in,
                              void* d_out, int out_size) {
    const float* h_wave      = (const float*)d_in[0];
    const int*   solution    = (const int*)d_in[1];
    const float* selrec      = (const float*)d_in[2];
    const int*   pre_action  = (const int*)d_in[3];
    const unsigned char* mt  = (const unsigned char*)d_in[4];
    const float* Wn  = (const float*)d_in[5];
    const float* Wg  = (const float*)d_in[6];
    const float* rmWQ = (const float*)d_in[7];
    const float* rmWK = (const float*)d_in[8];
    const float* rw1 = (const float*)d_in[9];
    const float* rb1 = (const float*)d_in[10];
    const float* rw2 = (const float*)d_in[11];
    const float* rb2 = (const float*)d_in[12];
    const float* rw3 = (const float*)d_in[13];
    const float* rb3 = (const float*)d_in[14];
    const float* i1q = (const float*)d_in[15];
    const float* i1k = (const float*)d_in[16];
    const float* i2q = (const float*)d_in[17];
    const float* i2k = (const float*)d_in[18];
    const float* ew1 = (const float*)d_in[19];
    const float* eb1 = (const float*)d_in[20];
    const float* ew2 = (const float*)d_in[21];
    const float* eb2 = (const float*)d_in[22];
    const float* ew3 = (const float*)d_in[23];
    const float* eb3 = (const float*)d_in[24];
    float* out = (float*)d_out;

    k_prep<<<BB, DD>>>(h_wave, Wg);
    k_hhat<<<MM/8, DD>>>(h_wave, Wn);
    {
        dim3 gm(4, 128);
        k_mmat<<<gm, DD>>>(rmWQ, rmWK);
    }
    {
        dim3 gg(201, 8);
        k_pgemm<<<gg, 128>>>();
    }
    k_t1<<<BB, 256>>>(solution, selrec, pre_action, rw1, rb1, rw2, rb2, rw3, rb3);
    {
        dim3 gq(16, BB);
        k_qt<<<gq, 128>>>(i1q, i1k, i2q, i2k);
    }
    {
        dim3 gr(2, BB);
        k_rc<<<gr, 128>>>(solution, ew1, eb1);
    }
    {
        dim3 gt(NT2B, BB);
        k_t2<<<gt, 256>>>(mt, ew2, eb2, ew3, eb3);
    }
    k_red<<<1, 64>>>(out);
}

// round 5
// speedup vs baseline: 16.6349x; 1.0512x over previous
#include <cuda_runtime.h>

#define BB 64
#define N1 201
#define DD 128
#define HF 100
#define MM (BB*N1)          // 12864
#define NEGV -1e20f
#define NT2B 101            // t2 blocks per batch (ceil(201/2))

typedef unsigned long long ull;

// ---------------- scratch ----------------
__device__ __align__(16) float g_gv[BB*DD];
__device__ __align__(16) float g_hhat[MM*DD];        // 6.6 MB
__device__ __align__(16) float g_M[4*DD*DD];         // WQ_h @ WK_h^T (removal)
__device__ __align__(16) float g_proj[4*MM*DD];      // P = hhat @ M_h (26 MB)
__device__ __align__(16) float g_qt[16*BB*DD];       // folded qtilde vectors
__device__ __align__(16) float g_rc[MM*32];
__device__ __align__(16) float g_cc[MM*32];
__device__ int   g_a1[BB];
__device__ float g_ll1[BB];
__device__ ull   g_pkey[BB*NT2B];
__device__ float g_psum[BB*NT2B];

// ---------------- f32x2 helpers ----------------
__device__ __forceinline__ ull ffma2(ull a, ull b, ull c) {
    ull d;
    asm("fma.rn.f32x2 %0, %1, %2, %3;" : "=l"(d) : "l"(a), "l"(b), "l"(c));
    return d;
}
__device__ __forceinline__ ull pack2(float x) {
    ull r;
    asm("mov.b64 %0, {%1, %2};" : "=l"(r) : "f"(x), "f"(x));
    return r;
}
__device__ __forceinline__ ull pack2v(float lo, float hi) {
    ull r;
    asm("mov.b64 %0, {%1, %2};" : "=l"(r) : "f"(lo), "f"(hi));
    return r;
}
__device__ __forceinline__ void unpack2(ull v, float& lo, float& hi) {
    asm("mov.b64 {%0, %1}, %2;" : "=f"(lo), "=f"(hi) : "l"(v));
}

// ---------------- K1: hmax + g = hmax @ Wg ----------------
__global__ void k_prep(const float* __restrict__ hw, const float* __restrict__ Wg) {
    __shared__ float hm[DD];
    int b = blockIdx.x, d = threadIdx.x;
    const float* p = hw + (size_t)b*N1*DD + d;
    float m = -3.4e38f;
    for (int n = 0; n < N1; n++) m = fmaxf(m, p[n*DD]);
    hm[d] = m;
    __syncthreads();
    float s = 0.f;
    for (int k = 0; k < DD; k++) s += hm[k] * Wg[k*DD + d];
    g_gv[b*DD + d] = s;
}

// ---------------- K2: h_hat = h_wave @ Wn + g[b] — f32x2, 16 rows/block ----------------
__global__ __launch_bounds__(128) void k_hhat(const float* __restrict__ hw,
                                              const float* __restrict__ Wn) {
    __shared__ float Asf[DD][18];   // [k][pair*2 + half], pad 18 for banks
    int r0 = blockIdx.x * 16;
    int tid = threadIdx.x;          // load role: k = tid; compute role: d = tid
    #pragma unroll
    for (int rr = 0; rr < 16; rr++) {
        Asf[tid][(rr & 7)*2 + (rr >> 3)] = hw[(size_t)(r0+rr)*DD + tid];
    }
    __syncthreads();
    ull acc[8];
    #pragma unroll
    for (int p = 0; p < 8; p++) {
        int bl = (r0 + p) / N1, bh = (r0 + p + 8) / N1;
        acc[p] = pack2v(g_gv[bl*DD + tid], g_gv[bh*DD + tid]);
    }
    #pragma unroll 4
    for (int k = 0; k < DD; k++) {
        ull w2 = pack2(Wn[k*DD + tid]);
        const ull* arow = (const ull*)&Asf[k][0];
        #pragma unroll
        for (int p = 0; p < 8; p++) acc[p] = ffma2(arow[p], w2, acc[p]);
    }
    #pragma unroll
    for (int p = 0; p < 8; p++) {
        float lo, hi; unpack2(acc[p], lo, hi);
        g_hhat[(size_t)(r0+p)*DD + tid]   = lo;
        g_hhat[(size_t)(r0+p+8)*DD + tid] = hi;
    }
}

// ---------------- K3: M_h = rmWQ_h @ rmWK_h^T (tiny) ----------------
__global__ void k_mmat(const float* __restrict__ WQ, const float* __restrict__ WK) {
    __shared__ float wk[DD];
    int h = blockIdx.x, dp = blockIdx.y;
    int tid = threadIdx.x;
    wk[tid] = WK[(size_t)(h*DD + dp)*DD + tid];
    __syncthreads();
    const float4* q4 = (const float4*)(WQ + (size_t)(h*DD + tid)*DD);
    const float4* k4 = (const float4*)wk;
    float s = 0.f;
    #pragma unroll
    for (int c = 0; c < 32; c++) {
        float4 a = q4[c], bq = k4[c];
        s += a.x*bq.x + a.y*bq.y + a.z*bq.z + a.w*bq.w;
    }
    g_M[(size_t)(h*DD + tid)*DD + dp] = s;
}

// ---------------- K4: P = hhat @ M — f32x2 GEMM, 192x64 tile, 12x4/thread ----------------
__global__ __launch_bounds__(256, 1) void k_pgemm() {
    __shared__ __align__(16) float As[16][194];   // pad 194: conflict-free transpose STS
    __shared__ __align__(16) float Bs[16][64];
    int bm = blockIdx.x;              // 0..66  (67*192 = 12864 exact)
    int bn = blockIdx.y;              // 0..7
    int h  = bn >> 1;
    int d0 = (bn & 1) * 64;
    const float* W = g_M + (size_t)h * DD * DD;

    int tid = threadIdx.x;
    int tx = tid & 15, ty = tid >> 4;              // tx: n-group (4 cols), ty: m-group (12 rows)
    int brow = tid >> 4, bc0 = (tid & 15) * 4;
    ull c2[6][4] = {};

    for (int k0 = 0; k0 < DD; k0 += 16) {
        #pragma unroll
        for (int q = 0; q < 3; q++) {
            int idx = tid + 256*q;                 // 0..767
            int row = idx >> 2, c4 = (idx & 3) * 4;
            float4 a = *(const float4*)(g_hhat + (size_t)(bm*192 + row)*DD + k0 + c4);
            As[c4+0][row] = a.x; As[c4+1][row] = a.y;
            As[c4+2][row] = a.z; As[c4+3][row] = a.w;
        }
        *(float4*)&Bs[brow][bc0] = *(const float4*)(W + (size_t)(k0+brow)*DD + d0 + bc0);
        __syncthreads();
        #pragma unroll
        for (int kk = 0; kk < 16; kk++) {
            const ull* ap = (const ull*)&As[kk][ty*12];
            float4 bv = *(const float4*)&Bs[kk][tx*4];
            ull b0 = pack2(bv.x), b1 = pack2(bv.y), b2 = pack2(bv.z), b3 = pack2(bv.w);
            #pragma unroll
            for (int p = 0; p < 6; p++) {
                ull a2 = ap[p];
                c2[p][0] = ffma2(a2, b0, c2[p][0]);
                c2[p][1] = ffma2(a2, b1, c2[p][1]);
                c2[p][2] = ffma2(a2, b2, c2[p][2]);
                c2[p][3] = ffma2(a2, b3, c2[p][3]);
            }
        }
        __syncthreads();
    }
    float* out = g_proj + (size_t)h * MM * DD;
    int row0 = bm*192 + ty*12, col0 = d0 + tx*4;
    #pragma unroll
    for (int p = 0; p < 6; p++) {
        float l0,h0,l1,h1,l2,h2,l3,h3;
        unpack2(c2[p][0], l0, h0); unpack2(c2[p][1], l1, h1);
        unpack2(c2[p][2], l2, h2); unpack2(c2[p][3], l3, h3);
        float4 v0; v0.x=l0; v0.y=l1; v0.z=l2; v0.w=l3;
        float4 v1; v1.x=h0; v1.y=h1; v1.z=h2; v1.w=h3;
        *(float4*)(out + (size_t)(row0 + 2*p + 0)*DD + col0) = v0;
        *(float4*)(out + (size_t)(row0 + 2*p + 1)*DD + col0) = v1;
    }
}

// ---------------- K5: removal — warp-cooperative compat + MLP (512 threads) ----------------
__global__ __launch_bounds__(512) void k_t1(const int* __restrict__ sol_g,
                     const float* __restrict__ selrec,
                     const int* __restrict__ pre_action,
                     const float* __restrict__ w1, const float* __restrict__ b1,
                     const float* __restrict__ w2, const float* __restrict__ b2,
                     const float* __restrict__ w3, const float* __restrict__ b3) {
    __shared__ int sol[N1], inv[N1];
    __shared__ float feat_sh[HF][13];
    __shared__ float t1s[HF];
    __shared__ float W1[12*32], B1[32], W2s[32*32], B2s[32], W3s[32];
    int b = blockIdx.x, tid = threadIdx.x;
    int wid = tid >> 5, lane = tid & 31;
    for (int i = tid; i < N1; i += 512) sol[i] = sol_g[b*N1 + i];
    for (int i = tid; i < 12*32; i += 512) W1[i] = w1[i];
    for (int i = tid; i < 32*32; i += 512) W2s[i] = w2[i];
    if (tid < 32) { B1[tid] = b1[tid]; B2s[tid] = b2[tid]; W3s[tid] = w3[tid]; }
    __syncthreads();
    for (int i = tid; i < N1; i += 512) inv[sol[i]] = i;
    __syncthreads();

    for (int item = wid; item < 200; item += 16) {
        int n = item + 1;
        int half = (item < HF) ? 0 : 1;
        int m = (item < HF) ? item : (item - HF);
        int ipre  = inv[n];
        int ipost = sol[sol[n]];
        float4 xn = ((const float4*)(g_hhat + (size_t)(b*N1 + n    )*DD))[lane];
        float4 xp = ((const float4*)(g_hhat + (size_t)(b*N1 + ipost)*DD))[lane];
        #pragma unroll
        for (int h = 0; h < 4; h++) {
            float4 pp = ((const float4*)(g_proj + ((size_t)h*MM + b*N1 + ipre)*DD))[lane];
            float4 pn = ((const float4*)(g_proj + ((size_t)h*MM + b*N1 + n   )*DD))[lane];
            float s = pp.x*xn.x + pp.y*xn.y + pp.z*xn.z + pp.w*xn.w
                    + pn.x*xp.x + pn.y*xp.y + pn.z*xp.z + pn.w*xp.w
                    - (pp.x*xp.x + pp.y*xp.y + pp.z*xp.z + pp.w*xp.w);
            #pragma unroll
            for (int off = 16; off > 0; off >>= 1) s += __shfl_xor_sync(0xFFFFFFFF, s, off);
            if (lane == 0) feat_sh[m][half*4 + h] = s;
        }
    }
    for (int l = tid; l < 4*HF; l += 512) {
        int s = l / HF, m = l % HF;
        feat_sh[m][8 + s] = selrec[b*4*HF + l];
    }
    __syncthreads();

    if (tid < HF) {
        int m = tid;
        float h1[32];
        #pragma unroll
        for (int c = 0; c < 32; c++) {
            float s = B1[c];
            #pragma unroll
            for (int f = 0; f < 12; f++) s += feat_sh[m][f] * W1[f*32 + c];
            h1[c] = fmaxf(s, 0.f);
        }
        float h2[32];
        #pragma unroll
        for (int c = 0; c < 32; c++) {
            float s = B2s[c];
            #pragma unroll
            for (int f = 0; f < 32; f++) s += h1[f] * W2s[f*32 + c];
            h2[c] = fmaxf(s, 0.f);
        }
        float o = b3[0];
        #pragma unroll
        for (int c = 0; c < 32; c++) o += h2[c] * W3s[c];
        float t1 = tanhf(o) * 6.0f;
        if (pre_action[0] > 0 && m == pre_action[b*2]) t1 = NEGV;
        t1s[m] = t1;
    }
    __syncthreads();
    if (tid == 0) {
        float mx = t1s[0]; int am = 0;
        for (int m = 1; m < HF; m++) if (t1s[m] > mx) { mx = t1s[m]; am = m; }
        float se = 0.f;
        for (int m = 0; m < HF; m++) se += expf(t1s[m] - mx);
        g_a1[b] = am;
        g_ll1[b] = -logf(se);
    }
}

// ---------------- K6: qtilde = Wk @ (Wq^T h_sel) (16 per batch) ----------------
__global__ void k_qt(const float* __restrict__ i1q, const float* __restrict__ i1k,
                     const float* __restrict__ i2q, const float* __restrict__ i2k) {
    __shared__ float hp[DD];
    __shared__ float u[DD];
    __shared__ float Ws[DD*33];
    int x = blockIdx.x;               // t*4+h
    int t = x >> 2, h = x & 3;
    int b = blockIdx.y;
    int tid = threadIdx.x;
    int a1 = g_a1[b];
    int pos = (t < 2) ? (1 + a1) : (1 + HF + a1);
    hp[tid] = g_hhat[(size_t)(b*N1 + pos)*DD + tid];
    __syncthreads();
    const float* Wq = ((t & 1) ? i2q : i1q) + (size_t)h*DD*DD;
    const float* Wk = ((t & 1) ? i2k : i1k) + (size_t)h*DD*DD;
    float su = 0.f;
    for (int k = 0; k < DD; k++) su += hp[k] * Wq[k*DD + tid];
    u[tid] = su;
    __syncthreads();
    float acc = 0.f;
    for (int e0 = 0; e0 < DD; e0 += 32) {
        for (int l = tid; l < DD*32; l += 128) {
            int dd = l >> 5, ee = l & 31;
            Ws[dd*33 + ee] = Wk[(size_t)dd*DD + e0 + ee];
        }
        __syncthreads();
        const float* wr = Ws + tid*33;
        #pragma unroll
        for (int ee = 0; ee < 32; ee++) acc += u[e0+ee] * wr[ee];
        __syncthreads();
    }
    g_qt[((size_t)x*BB + b)*DD + tid] = acc;
}

// ---------------- K7: row/col layer-1 contributions ----------------
__global__ void k_rc(const int* __restrict__ sol_g,
                     const float* __restrict__ w1, const float* __restrict__ b1v) {
    __shared__ __align__(16) float qv[16*DD];
    __shared__ float W1[16*32], B1[32];
    int b = blockIdx.y;
    int tid = threadIdx.x;
    int i = blockIdx.x * 128 + tid;
    for (int l = tid; l < 16*DD; l += 128) {
        int x = l >> 7, d = l & 127;
        qv[l] = g_qt[((size_t)x*BB + b)*DD + d];
    }
    for (int l = tid; l < 16*32; l += 128) W1[l] = w1[l];
    if (tid < 32) B1[tid] = b1v[tid];
    __syncthreads();
    if (i < N1) {
        const float invs = 0.08838834764831845f;  // 1/sqrt(128)
        int si = sol_g[b*N1 + i];
        const float4* hi4 = (const float4*)(g_hhat + (size_t)(b*N1 + i )*DD);
        const float4* hs4 = (const float4*)(g_hhat + (size_t)(b*N1 + si)*DD);
        float s[16] = {};
        for (int c = 0; c < 32; c++) {
            float4 xi = hi4[c], xs = hs4[c];
            #pragma unroll
            for (int h = 0; h < 4; h++) {
                float4 q0 = ((const float4*)(qv + (0*4+h)*DD))[c];
                float4 q1 = ((const float4*)(qv + (1*4+h)*DD))[c];
                float4 q2 = ((const float4*)(qv + (2*4+h)*DD))[c];
                float4 q3 = ((const float4*)(qv + (3*4+h)*DD))[c];
                s[h]    += q0.x*xi.x + q0.y*xi.y + q0.z*xi.z + q0.w*xi.w;
                s[4+h]  += q1.x*xs.x + q1.y*xs.y + q1.z*xs.z + q1.w*xs.w;
                s[8+h]  += q2.x*xi.x + q2.y*xi.y + q2.z*xi.z + q2.w*xi.w;
                s[12+h] += q3.x*xs.x + q3.y*xs.y + q3.z*xs.z + q3.w*xs.w;
            }
        }
        #pragma unroll
        for (int c = 0; c < 32; c++) {
            float rs = 0.f, cs = B1[c];
            #pragma unroll
            for (int f = 0; f < 8; f++) {
                rs += s[f]*invs   * W1[f*32 + c];
                cs += s[8+f]*invs * W1[(8+f)*32 + c];
            }
            g_rc[(size_t)(b*N1 + i)*32 + c] = rs;
            g_cc[(size_t)(b*N1 + i)*32 + c] = cs;
        }
    }
}

// ---------------- K8: fused reinsertion MLP + in-block reduction — f32x2, kk-outer ----------------
__global__ __launch_bounds__(256, 1) void k_t2(const unsigned char* __restrict__ maskt,
                                               const float* __restrict__ w2, const float* __restrict__ b2,
                                               const float* __restrict__ w3, const float* __restrict__ b3) {
    __shared__ __align__(16) float W2[32*32];
    __shared__ __align__(8)  float B2[32];
    __shared__ float W3[32];
    __shared__ float rc0[32], rc1[32];
    __shared__ float cjs[N1*33];
    __shared__ ull   skw[8];
    __shared__ float ssw[8];
    __shared__ float B3;
    int b = blockIdx.y;
    int i0 = blockIdx.x * 2;
    int tid = threadIdx.x;
    int wid = tid >> 5, lane = tid & 31;
    for (int l = tid; l < 1024; l += 256) W2[l] = w2[l];
    if (tid < 32) { B2[tid] = b2[tid]; W3[tid] = w3[tid]; }
    if (tid == 0) B3 = b3[0];
    if (tid < 32)      rc0[tid]    = g_rc[(size_t)(b*N1 + i0)*32 + tid];
    else if (tid < 64) rc1[tid-32] = (i0+1 < N1) ? g_rc[(size_t)(b*N1 + i0 + 1)*32 + (tid-32)] : 0.f;
    for (int l = tid; l < N1*32; l += 256) {
        int j = l >> 5, c = l & 31;
        cjs[j*33 + c] = g_cc[(size_t)(b*N1 + j)*32 + c];
    }
    __syncthreads();

    ull bk = 0; float bs = 0.f;
    int j = tid;
    if (j < N1) {
        const ull* B2d = (const ull*)B2;
        const float* cj = cjs + j*33;
        ull acc0[16], acc1[16];
        #pragma unroll
        for (int q = 0; q < 16; q++) { acc0[q] = B2d[q]; acc1[q] = B2d[q]; }
        #pragma unroll 4
        for (int kk = 0; kk < 32; kk++) {
            float cjk = cj[kk];
            ull hh0 = pack2(fmaxf(rc0[kk] + cjk, 0.f));
            ull hh1 = pack2(fmaxf(rc1[kk] + cjk, 0.f));
            const ull* wrow = (const ull*)(W2 + kk*32);
            #pragma unroll
            for (int q = 0; q < 16; q++) {
                ull w = wrow[q];
                acc0[q] = ffma2(hh0, w, acc0[q]);
                acc1[q] = ffma2(hh1, w, acc1[q]);
            }
        }
        #pragma unroll
        for (int it = 0; it < 2; it++) {
            int i = i0 + it;
            if (i < N1) {
                float o = B3;
                #pragma unroll
                for (int q = 0; q < 16; q++) {
                    float lo, hi;
                    unpack2(it == 0 ? acc0[q] : acc1[q], lo, hi);
                    o += fmaxf(lo, 0.f) * W3[2*q] + fmaxf(hi, 0.f) * W3[2*q+1];
                }
                float t2v = maskt[((size_t)b*N1 + i)*N1 + j] ? NEGV : tanhf(o)*6.0f;
                unsigned int lin = (unsigned int)(i*N1 + j);
                unsigned int u = __float_as_uint(t2v);
                unsigned int ord = (u >> 31) ? ~u : (u | 0x80000000u);
                ull key = ((ull)ord << 32) | (0xFFFFFFFFu - lin);
                if (key > bk) bk = key;
                bs += expf(t2v - 6.f);
            }
        }
    }
    #pragma unroll
    for (int off = 16; off > 0; off >>= 1) {
        ull ok = __shfl_xor_sync(0xFFFFFFFF, bk, off);
        float os = __shfl_xor_sync(0xFFFFFFFF, bs, off);
        if (ok > bk) bk = ok;
        bs += os;
    }
    if (lane == 0) { skw[wid] = bk; ssw[wid] = bs; }
    __syncthreads();
    if (tid == 0) {
        ull k = skw[0]; float s = ssw[0];
        #pragma unroll
        for (int w = 1; w < 8; w++) {
            if (skw[w] > k) k = skw[w];
            s += ssw[w];
        }
        g_pkey[b*NT2B + blockIdx.x] = k;
        g_psum[b*NT2B + blockIdx.x] = s;
    }
}

// ---------------- K9: final per-batch reduce (deterministic) ----------------
__global__ void k_red(float* __restrict__ out) {
    int b = threadIdx.x;
    if (b < BB) {
        ull bk = 0; float s = 0.f;
        for (int p = 0; p < NT2B; p++) {
            ull k = g_pkey[b*NT2B + p];
            if (k > bk) bk = k;
            s += g_psum[b*NT2B + p];
        }
        unsigned int ord = (unsigned int)(bk >> 32);
        unsigned int u = (ord & 0x80000000u) ? (ord ^ 0x80000000u) : ~ord;
        float vmax = __uint_as_float(u);
        unsigned int lin = 0xFFFFFFFFu - (unsigned int)(bk & 0xFFFFFFFFu);
        float ll2 = vmax - 6.f - logf(s);
        out[b*3 + 0] = (float)g_a1[b];
        out[b*3 + 1] = (float)(lin / N1);
        out[b*3 + 2] = (float)(lin % N1);
        out[BB*3 + b] = g_ll1[b] + ll2;
    }
}

// ---------------- launch ----------------
extern "C" void kernel_launch(void* const* d_in, const int* in_sizes, int n_in,
                              void* d_out, int out_size) {
    const float* h_wave      = (const float*)d_in[0];
    const int*   solution    = (const int*)d_in[1];
    const float* selrec      = (const float*)d_in[2];
    const int*   pre_action  = (const int*)d_in[3];
    const unsigned char* mt  = (const unsigned char*)d_in[4];
    const float* Wn  = (const float*)d_in[5];
    const float* Wg  = (const float*)d_in[6];
    const float* rmWQ = (const float*)d_in[7];
    const float* rmWK = (const float*)d_in[8];
    const float* rw1 = (const float*)d_in[9];
    const float* rb1 = (const float*)d_in[10];
    const float* rw2 = (const float*)d_in[11];
    const float* rb2 = (const float*)d_in[12];
    const float* rw3 = (const float*)d_in[13];
    const float* rb3 = (const float*)d_in[14];
    const float* i1q = (const float*)d_in[15];
    const float* i1k = (const float*)d_in[16];
    const float* i2q = (const float*)d_in[17];
    const float* i2k = (const float*)d_in[18];
    const float* ew1 = (const float*)d_in[19];
    const float* eb1 = (const float*)d_in[20];
    const float* ew2 = (const float*)d_in[21];
    const float* eb2 = (const float*)d_in[22];
    const float* ew3 = (const float*)d_in[23];
    const float* eb3 = (const float*)d_in[24];
    float* out = (float*)d_out;

    k_prep<<<BB, DD>>>(h_wave, Wg);
    k_hhat<<<MM/16, DD>>>(h_wave, Wn);
    {
        dim3 gm(4, 128);
        k_mmat<<<gm, DD>>>(rmWQ, rmWK);
    }
    {
        dim3 gg(67, 8);
        k_pgemm<<<gg, 256>>>();
    }
    k_t1<<<BB, 512>>>(solution, selrec, pre_action, rw1, rb1, rw2, rb2, rw3, rb3);
    {
        dim3 gq(16, BB);
        k_qt<<<gq, 128>>>(i1q, i1k, i2q, i2k);
    }
    {
        dim3 gr(2, BB);
        k_rc<<<gr, 128>>>(solution, ew1, eb1);
    }
    {
        dim3 gt(NT2B, BB);
        k_t2<<<gt, 256>>>(mt, ew2, eb2, ew3, eb3);
    }
    k_red<<<1, 64>>>(out);
}

// round 6
// speedup vs baseline: 16.7101x; 1.0045x over previous
#include <cuda_runtime.h>

#define BB 64
#define N1 201
#define DD 128
#define HF 100
#define MM (BB*N1)          // 12864
#define NEGV -1e20f
#define NT2B 101            // t2 blocks per batch (ceil(201/2))

typedef unsigned long long ull;

// ---------------- scratch ----------------
__device__ __align__(16) float g_gv[BB*DD];
__device__ __align__(16) float g_hhat[MM*DD];        // 6.6 MB
__device__ __align__(16) float g_M[4*DD*DD];         // WQ_h @ WK_h^T (removal)
__device__ __align__(16) float g_proj[4*MM*DD];      // P = hhat @ M_h (26 MB)
__device__ __align__(16) float g_qt[16*BB*DD];       // folded qtilde vectors
__device__ __align__(16) float g_rc[MM*32];
__device__ __align__(16) float g_cc[MM*32];
__device__ int   g_a1[BB];
__device__ float g_ll1[BB];
__device__ ull   g_pkey[BB*NT2B];
__device__ float g_psum[BB*NT2B];

// ---------------- f32x2 helpers ----------------
__device__ __forceinline__ ull ffma2(ull a, ull b, ull c) {
    ull d;
    asm("fma.rn.f32x2 %0, %1, %2, %3;" : "=l"(d) : "l"(a), "l"(b), "l"(c));
    return d;
}
__device__ __forceinline__ ull pack2(float x) {
    ull r;
    asm("mov.b64 %0, {%1, %2};" : "=l"(r) : "f"(x), "f"(x));
    return r;
}
__device__ __forceinline__ ull pack2v(float lo, float hi) {
    ull r;
    asm("mov.b64 %0, {%1, %2};" : "=l"(r) : "f"(lo), "f"(hi));
    return r;
}
__device__ __forceinline__ void unpack2(ull v, float& lo, float& hi) {
    asm("mov.b64 {%0, %1}, %2;" : "=f"(lo), "=f"(hi) : "l"(v));
}

// ---------------- K1: hmax + g = hmax @ Wg ----------------
__global__ void k_prep(const float* __restrict__ hw, const float* __restrict__ Wg) {
    __shared__ float hm[DD];
    int b = blockIdx.x, d = threadIdx.x;
    const float* p = hw + (size_t)b*N1*DD + d;
    float m = -3.4e38f;
    for (int n = 0; n < N1; n++) m = fmaxf(m, p[n*DD]);
    hm[d] = m;
    __syncthreads();
    float s = 0.f;
    for (int k = 0; k < DD; k++) s += hm[k] * Wg[k*DD + d];
    g_gv[b*DD + d] = s;
}

// ---------------- K2: h_hat = h_wave @ Wn + g[b] — f32x2, 16 rows/block ----------------
__global__ __launch_bounds__(128) void k_hhat(const float* __restrict__ hw,
                                              const float* __restrict__ Wn) {
    __shared__ float Asf[DD][18];   // [k][pair*2 + half], pad 18 for banks
    int r0 = blockIdx.x * 16;
    int tid = threadIdx.x;
    #pragma unroll
    for (int rr = 0; rr < 16; rr++) {
        Asf[tid][(rr & 7)*2 + (rr >> 3)] = hw[(size_t)(r0+rr)*DD + tid];
    }
    __syncthreads();
    ull acc[8];
    #pragma unroll
    for (int p = 0; p < 8; p++) {
        int bl = (r0 + p) / N1, bh = (r0 + p + 8) / N1;
        acc[p] = pack2v(g_gv[bl*DD + tid], g_gv[bh*DD + tid]);
    }
    #pragma unroll 4
    for (int k = 0; k < DD; k++) {
        ull w2 = pack2(Wn[k*DD + tid]);
        const ull* arow = (const ull*)&Asf[k][0];
        #pragma unroll
        for (int p = 0; p < 8; p++) acc[p] = ffma2(arow[p], w2, acc[p]);
    }
    #pragma unroll
    for (int p = 0; p < 8; p++) {
        float lo, hi; unpack2(acc[p], lo, hi);
        g_hhat[(size_t)(r0+p)*DD + tid]   = lo;
        g_hhat[(size_t)(r0+p+8)*DD + tid] = hi;
    }
}

// ---------------- K3: M_h = rmWQ_h @ rmWK_h^T (tiny) ----------------
__global__ void k_mmat(const float* __restrict__ WQ, const float* __restrict__ WK) {
    __shared__ float wk[DD];
    int h = blockIdx.x, dp = blockIdx.y;
    int tid = threadIdx.x;
    wk[tid] = WK[(size_t)(h*DD + dp)*DD + tid];
    __syncthreads();
    const float4* q4 = (const float4*)(WQ + (size_t)(h*DD + tid)*DD);
    const float4* k4 = (const float4*)wk;
    float s = 0.f;
    #pragma unroll
    for (int c = 0; c < 32; c++) {
        float4 a = q4[c], bq = k4[c];
        s += a.x*bq.x + a.y*bq.y + a.z*bq.z + a.w*bq.w;
    }
    g_M[(size_t)(h*DD + tid)*DD + dp] = s;
}

// ---------------- K4: P = hhat @ M — f32x2 GEMM, 192x64 tile, double-buffered ----------------
__global__ __launch_bounds__(256, 1) void k_pgemm() {
    __shared__ __align__(16) float As[2][16][194];   // pad 194: conflict-free transpose STS
    __shared__ __align__(16) float Bs[2][16][64];
    int bm = blockIdx.x;              // 0..66  (67*192 = 12864 exact)
    int bn = blockIdx.y;              // 0..7
    int h  = bn >> 1;
    int d0 = (bn & 1) * 64;
    const float* W = g_M + (size_t)h * DD * DD;

    int tid = threadIdx.x;
    int tx = tid & 15, ty = tid >> 4;
    int brow = tid >> 4, bc0 = (tid & 15) * 4;
    ull c2[6][4] = {};

    int arowv[3], ac4v[3];
    #pragma unroll
    for (int q = 0; q < 3; q++) {
        int idx = tid + 256*q;
        arowv[q] = idx >> 2;
        ac4v[q]  = (idx & 3) * 4;
    }

    float4 aR[3], bR;
    // prologue: load tile k0=0
    #pragma unroll
    for (int q = 0; q < 3; q++)
        aR[q] = *(const float4*)(g_hhat + (size_t)(bm*192 + arowv[q])*DD + 0 + ac4v[q]);
    bR = *(const float4*)(W + (size_t)(0+brow)*DD + d0 + bc0);
    #pragma unroll
    for (int q = 0; q < 3; q++) {
        As[0][ac4v[q]+0][arowv[q]] = aR[q].x; As[0][ac4v[q]+1][arowv[q]] = aR[q].y;
        As[0][ac4v[q]+2][arowv[q]] = aR[q].z; As[0][ac4v[q]+3][arowv[q]] = aR[q].w;
    }
    *(float4*)&Bs[0][brow][bc0] = bR;
    __syncthreads();

    int buf = 0;
    for (int k0 = 0; k0 < DD; k0 += 16) {
        bool more = (k0 + 16 < DD);
        if (more) {
            #pragma unroll
            for (int q = 0; q < 3; q++)
                aR[q] = *(const float4*)(g_hhat + (size_t)(bm*192 + arowv[q])*DD + (k0+16) + ac4v[q]);
            bR = *(const float4*)(W + (size_t)(k0+16+brow)*DD + d0 + bc0);
        }
        #pragma unroll
        for (int kk = 0; kk < 16; kk++) {
            const ull* ap = (const ull*)&As[buf][kk][ty*12];
            float4 bv = *(const float4*)&Bs[buf][kk][tx*4];
            ull b0 = pack2(bv.x), b1 = pack2(bv.y), b2 = pack2(bv.z), b3 = pack2(bv.w);
            #pragma unroll
            for (int p = 0; p < 6; p++) {
                ull a2 = ap[p];
                c2[p][0] = ffma2(a2, b0, c2[p][0]);
                c2[p][1] = ffma2(a2, b1, c2[p][1]);
                c2[p][2] = ffma2(a2, b2, c2[p][2]);
                c2[p][3] = ffma2(a2, b3, c2[p][3]);
            }
        }
        if (more) {
            #pragma unroll
            for (int q = 0; q < 3; q++) {
                As[buf^1][ac4v[q]+0][arowv[q]] = aR[q].x; As[buf^1][ac4v[q]+1][arowv[q]] = aR[q].y;
                As[buf^1][ac4v[q]+2][arowv[q]] = aR[q].z; As[buf^1][ac4v[q]+3][arowv[q]] = aR[q].w;
            }
            *(float4*)&Bs[buf^1][brow][bc0] = bR;
        }
        __syncthreads();
        buf ^= 1;
    }

    float* out = g_proj + (size_t)h * MM * DD;
    int row0 = bm*192 + ty*12, col0 = d0 + tx*4;
    #pragma unroll
    for (int p = 0; p < 6; p++) {
        float l0,h0,l1,h1,l2,h2,l3,h3;
        unpack2(c2[p][0], l0, h0); unpack2(c2[p][1], l1, h1);
        unpack2(c2[p][2], l2, h2); unpack2(c2[p][3], l3, h3);
        float4 v0; v0.x=l0; v0.y=l1; v0.z=l2; v0.w=l3;
        float4 v1; v1.x=h0; v1.y=h1; v1.z=h2; v1.w=h3;
        *(float4*)(out + (size_t)(row0 + 2*p + 0)*DD + col0) = v0;
        *(float4*)(out + (size_t)(row0 + 2*p + 1)*DD + col0) = v1;
    }
}

// ---------------- K5: removal — warp-cooperative compat + MLP (512 threads) ----------------
__global__ __launch_bounds__(512) void k_t1(const int* __restrict__ sol_g,
                     const float* __restrict__ selrec,
                     const int* __restrict__ pre_action,
                     const float* __restrict__ w1, const float* __restrict__ b1,
                     const float* __restrict__ w2, const float* __restrict__ b2,
                     const float* __restrict__ w3, const float* __restrict__ b3) {
    __shared__ int sol[N1], inv[N1];
    __shared__ float feat_sh[HF][13];
    __shared__ float t1s[HF];
    __shared__ float W1[12*32], B1[32], W2s[32*32], B2s[32], W3s[32];
    int b = blockIdx.x, tid = threadIdx.x;
    int wid = tid >> 5, lane = tid & 31;
    for (int i = tid; i < N1; i += 512) sol[i] = sol_g[b*N1 + i];
    for (int i = tid; i < 12*32; i += 512) W1[i] = w1[i];
    for (int i = tid; i < 32*32; i += 512) W2s[i] = w2[i];
    if (tid < 32) { B1[tid] = b1[tid]; B2s[tid] = b2[tid]; W3s[tid] = w3[tid]; }
    __syncthreads();
    for (int i = tid; i < N1; i += 512) inv[sol[i]] = i;
    __syncthreads();

    for (int item = wid; item < 200; item += 16) {
        int n = item + 1;
        int half = (item < HF) ? 0 : 1;
        int m = (item < HF) ? item : (item - HF);
        int ipre  = inv[n];
        int ipost = sol[sol[n]];
        float4 xn = ((const float4*)(g_hhat + (size_t)(b*N1 + n    )*DD))[lane];
        float4 xp = ((const float4*)(g_hhat + (size_t)(b*N1 + ipost)*DD))[lane];
        #pragma unroll
        for (int h = 0; h < 4; h++) {
            float4 pp = ((const float4*)(g_proj + ((size_t)h*MM + b*N1 + ipre)*DD))[lane];
            float4 pn = ((const float4*)(g_proj + ((size_t)h*MM + b*N1 + n   )*DD))[lane];
            float s = pp.x*xn.x + pp.y*xn.y + pp.z*xn.z + pp.w*xn.w
                    + pn.x*xp.x + pn.y*xp.y + pn.z*xp.z + pn.w*xp.w
                    - (pp.x*xp.x + pp.y*xp.y + pp.z*xp.z + pp.w*xp.w);
            #pragma unroll
            for (int off = 16; off > 0; off >>= 1) s += __shfl_xor_sync(0xFFFFFFFF, s, off);
            if (lane == 0) feat_sh[m][half*4 + h] = s;
        }
    }
    for (int l = tid; l < 4*HF; l += 512) {
        int s = l / HF, m = l % HF;
        feat_sh[m][8 + s] = selrec[b*4*HF + l];
    }
    __syncthreads();

    if (tid < HF) {
        int m = tid;
        float h1[32];
        #pragma unroll
        for (int c = 0; c < 32; c++) {
            float s = B1[c];
            #pragma unroll
            for (int f = 0; f < 12; f++) s += feat_sh[m][f] * W1[f*32 + c];
            h1[c] = fmaxf(s, 0.f);
        }
        float h2[32];
        #pragma unroll
        for (int c = 0; c < 32; c++) {
            float s = B2s[c];
            #pragma unroll
            for (int f = 0; f < 32; f++) s += h1[f] * W2s[f*32 + c];
            h2[c] = fmaxf(s, 0.f);
        }
        float o = b3[0];
        #pragma unroll
        for (int c = 0; c < 32; c++) o += h2[c] * W3s[c];
        float t1 = tanhf(o) * 6.0f;
        if (pre_action[0] > 0 && m == pre_action[b*2]) t1 = NEGV;
        t1s[m] = t1;
    }
    __syncthreads();
    if (tid == 0) {
        float mx = t1s[0]; int am = 0;
        for (int m = 1; m < HF; m++) if (t1s[m] > mx) { mx = t1s[m]; am = m; }
        float se = 0.f;
        for (int m = 0; m < HF; m++) se += expf(t1s[m] - mx);
        g_a1[b] = am;
        g_ll1[b] = -logf(se);
    }
}

// ---------------- K6: qtilde = Wk @ (Wq^T h_sel) (16 per batch) ----------------
__global__ void k_qt(const float* __restrict__ i1q, const float* __restrict__ i1k,
                     const float* __restrict__ i2q, const float* __restrict__ i2k) {
    __shared__ float hp[DD];
    __shared__ float u[DD];
    __shared__ float Ws[DD*33];
    int x = blockIdx.x;               // t*4+h
    int t = x >> 2, h = x & 3;
    int b = blockIdx.y;
    int tid = threadIdx.x;
    int a1 = g_a1[b];
    int pos = (t < 2) ? (1 + a1) : (1 + HF + a1);
    hp[tid] = g_hhat[(size_t)(b*N1 + pos)*DD + tid];
    __syncthreads();
    const float* Wq = ((t & 1) ? i2q : i1q) + (size_t)h*DD*DD;
    const float* Wk = ((t & 1) ? i2k : i1k) + (size_t)h*DD*DD;
    float su = 0.f;
    for (int k = 0; k < DD; k++) su += hp[k] * Wq[k*DD + tid];
    u[tid] = su;
    __syncthreads();
    float acc = 0.f;
    for (int e0 = 0; e0 < DD; e0 += 32) {
        for (int l = tid; l < DD*32; l += 128) {
            int dd = l >> 5, ee = l & 31;
            Ws[dd*33 + ee] = Wk[(size_t)dd*DD + e0 + ee];
        }
        __syncthreads();
        const float* wr = Ws + tid*33;
        #pragma unroll
        for (int ee = 0; ee < 32; ee++) acc += u[e0+ee] * wr[ee];
        __syncthreads();
    }
    g_qt[((size_t)x*BB + b)*DD + tid] = acc;
}

// ---------------- K7: row/col layer-1 contributions ----------------
__global__ void k_rc(const int* __restrict__ sol_g,
                     const float* __restrict__ w1, const float* __restrict__ b1v) {
    __shared__ __align__(16) float qv[16*DD];
    __shared__ float W1[16*32], B1[32];
    int b = blockIdx.y;
    int tid = threadIdx.x;
    int i = blockIdx.x * 128 + tid;
    for (int l = tid; l < 16*DD; l += 128) {
        int x = l >> 7, d = l & 127;
        qv[l] = g_qt[((size_t)x*BB + b)*DD + d];
    }
    for (int l = tid; l < 16*32; l += 128) W1[l] = w1[l];
    if (tid < 32) B1[tid] = b1v[tid];
    __syncthreads();
    if (i < N1) {
        const float invs = 0.08838834764831845f;  // 1/sqrt(128)
        int si = sol_g[b*N1 + i];
        const float4* hi4 = (const float4*)(g_hhat + (size_t)(b*N1 + i )*DD);
        const float4* hs4 = (const float4*)(g_hhat + (size_t)(b*N1 + si)*DD);
        float s[16] = {};
        for (int c = 0; c < 32; c++) {
            float4 xi = hi4[c], xs = hs4[c];
            #pragma unroll
            for (int h = 0; h < 4; h++) {
                float4 q0 = ((const float4*)(qv + (0*4+h)*DD))[c];
                float4 q1 = ((const float4*)(qv + (1*4+h)*DD))[c];
                float4 q2 = ((const float4*)(qv + (2*4+h)*DD))[c];
                float4 q3 = ((const float4*)(qv + (3*4+h)*DD))[c];
                s[h]    += q0.x*xi.x + q0.y*xi.y + q0.z*xi.z + q0.w*xi.w;
                s[4+h]  += q1.x*xs.x + q1.y*xs.y + q1.z*xs.z + q1.w*xs.w;
                s[8+h]  += q2.x*xi.x + q2.y*xi.y + q2.z*xi.z + q2.w*xi.w;
                s[12+h] += q3.x*xs.x + q3.y*xs.y + q3.z*xs.z + q3.w*xs.w;
            }
        }
        #pragma unroll
        for (int c = 0; c < 32; c++) {
            float rs = 0.f, cs = B1[c];
            #pragma unroll
            for (int f = 0; f < 8; f++) {
                rs += s[f]*invs   * W1[f*32 + c];
                cs += s[8+f]*invs * W1[(8+f)*32 + c];
            }
            g_rc[(size_t)(b*N1 + i)*32 + c] = rs;
            g_cc[(size_t)(b*N1 + i)*32 + c] = cs;
        }
    }
}

// ---------------- K8: fused reinsertion MLP + in-block reduction — f32x2, kk-outer ----------------
__global__ __launch_bounds__(256, 1) void k_t2(const unsigned char* __restrict__ maskt,
                                               const float* __restrict__ w2, const float* __restrict__ b2,
                                               const float* __restrict__ w3, const float* __restrict__ b3) {
    __shared__ __align__(16) float W2[32*32];
    __shared__ __align__(8)  float B2[32];
    __shared__ float W3[32];
    __shared__ float rc0[32], rc1[32];
    __shared__ float cjs[N1*33];
    __shared__ ull   skw[8];
    __shared__ float ssw[8];
    __shared__ float B3;
    int b = blockIdx.y;
    int i0 = blockIdx.x * 2;
    int tid = threadIdx.x;
    int wid = tid >> 5, lane = tid & 31;
    for (int l = tid; l < 1024; l += 256) W2[l] = w2[l];
    if (tid < 32) { B2[tid] = b2[tid]; W3[tid] = w3[tid]; }
    if (tid == 0) B3 = b3[0];
    if (tid < 32)      rc0[tid]    = g_rc[(size_t)(b*N1 + i0)*32 + tid];
    else if (tid < 64) rc1[tid-32] = (i0+1 < N1) ? g_rc[(size_t)(b*N1 + i0 + 1)*32 + (tid-32)] : 0.f;
    for (int l = tid; l < N1*32; l += 256) {
        int j = l >> 5, c = l & 31;
        cjs[j*33 + c] = g_cc[(size_t)(b*N1 + j)*32 + c];
    }
    __syncthreads();

    ull bk = 0; float bs = 0.f;
    int j = tid;
    if (j < N1) {
        const ull* B2d = (const ull*)B2;
        const float* cj = cjs + j*33;
        ull acc0[16], acc1[16];
        #pragma unroll
        for (int q = 0; q < 16; q++) { acc0[q] = B2d[q]; acc1[q] = B2d[q]; }
        #pragma unroll 4
        for (int kk = 0; kk < 32; kk++) {
            float cjk = cj[kk];
            ull hh0 = pack2(fmaxf(rc0[kk] + cjk, 0.f));
            ull hh1 = pack2(fmaxf(rc1[kk] + cjk, 0.f));
            const ulonglong2* wr = (const ulonglong2*)(W2 + kk*32);   // 128B-aligned rows
            #pragma unroll
            for (int q = 0; q < 8; q++) {
                ulonglong2 w = wr[q];
                acc0[2*q]   = ffma2(hh0, w.x, acc0[2*q]);
                acc0[2*q+1] = ffma2(hh0, w.y, acc0[2*q+1]);
                acc1[2*q]   = ffma2(hh1, w.x, acc1[2*q]);
                acc1[2*q+1] = ffma2(hh1, w.y, acc1[2*q+1]);
            }
        }
        #pragma unroll
        for (int it = 0; it < 2; it++) {
            int i = i0 + it;
            if (i < N1) {
                float o = B3;
                #pragma unroll
                for (int q = 0; q < 16; q++) {
                    float lo, hi;
                    unpack2(it == 0 ? acc0[q] : acc1[q], lo, hi);
                    o += fmaxf(lo, 0.f) * W3[2*q] + fmaxf(hi, 0.f) * W3[2*q+1];
                }
                float t2v = maskt[((size_t)b*N1 + i)*N1 + j] ? NEGV : tanhf(o)*6.0f;
                unsigned int lin = (unsigned int)(i*N1 + j);
                unsigned int u = __float_as_uint(t2v);
                unsigned int ord = (u >> 31) ? ~u : (u | 0x80000000u);
                ull key = ((ull)ord << 32) | (0xFFFFFFFFu - lin);
                if (key > bk) bk = key;
                bs += expf(t2v - 6.f);
            }
        }
    }
    #pragma unroll
    for (int off = 16; off > 0; off >>= 1) {
        ull ok = __shfl_xor_sync(0xFFFFFFFF, bk, off);
        float os = __shfl_xor_sync(0xFFFFFFFF, bs, off);
        if (ok > bk) bk = ok;
        bs += os;
    }
    if (lane == 0) { skw[wid] = bk; ssw[wid] = bs; }
    __syncthreads();
    if (tid == 0) {
        ull k = skw[0]; float s = ssw[0];
        #pragma unroll
        for (int w = 1; w < 8; w++) {
            if (skw[w] > k) k = skw[w];
            s += ssw[w];
        }
        g_pkey[b*NT2B + blockIdx.x] = k;
        g_psum[b*NT2B + blockIdx.x] = s;
    }
}

// ---------------- K9: final per-batch reduce (deterministic) ----------------
__global__ void k_red(float* __restrict__ out) {
    int b = threadIdx.x;
    if (b < BB) {
        ull bk = 0; float s = 0.f;
        for (int p = 0; p < NT2B; p++) {
            ull k = g_pkey[b*NT2B + p];
            if (k > bk) bk = k;
            s += g_psum[b*NT2B + p];
        }
        unsigned int ord = (unsigned int)(bk >> 32);
        unsigned int u = (ord & 0x80000000u) ? (ord ^ 0x80000000u) : ~ord;
        float vmax = __uint_as_float(u);
        unsigned int lin = 0xFFFFFFFFu - (unsigned int)(bk & 0xFFFFFFFFu);
        float ll2 = vmax - 6.f - logf(s);
        out[b*3 + 0] = (float)g_a1[b];
        out[b*3 + 1] = (float)(lin / N1);
        out[b*3 + 2] = (float)(lin % N1);
        out[BB*3 + b] = g_ll1[b] + ll2;
    }
}

// ---------------- launch ----------------
extern "C" void kernel_launch(void* const* d_in, const int* in_sizes, int n_in,
                              void* d_out, int out_size) {
    const float* h_wave      = (const float*)d_in[0];
    const int*   solution    = (const int*)d_in[1];
    const float* selrec      = (const float*)d_in[2];
    const int*   pre_action  = (const int*)d_in[3];
    const unsigned char* mt  = (const unsigned char*)d_in[4];
    const float* Wn  = (const float*)d_in[5];
    const float* Wg  = (const float*)d_in[6];
    const float* rmWQ = (const float*)d_in[7];
    const float* rmWK = (const float*)d_in[8];
    const float* rw1 = (const float*)d_in[9];
    const float* rb1 = (const float*)d_in[10];
    const float* rw2 = (const float*)d_in[11];
    const float* rb2 = (const float*)d_in[12];
    const float* rw3 = (const float*)d_in[13];
    const float* rb3 = (const float*)d_in[14];
    const float* i1q = (const float*)d_in[15];
    const float* i1k = (const float*)d_in[16];
    const float* i2q = (const float*)d_in[17];
    const float* i2k = (const float*)d_in[18];
    const float* ew1 = (const float*)d_in[19];
    const float* eb1 = (const float*)d_in[20];
    const float* ew2 = (const float*)d_in[21];
    const float* eb2 = (const float*)d_in[22];
    const float* ew3 = (const float*)d_in[23];
    const float* eb3 = (const float*)d_in[24];
    float* out = (float*)d_out;

    k_prep<<<BB, DD>>>(h_wave, Wg);
    k_hhat<<<MM/16, DD>>>(h_wave, Wn);
    {
        dim3 gm(4, 128);
        k_mmat<<<gm, DD>>>(rmWQ, rmWK);
    }
    {
        dim3 gg(67, 8);
        k_pgemm<<<gg, 256>>>();
    }
    k_t1<<<BB, 512>>>(solution, selrec, pre_action, rw1, rb1, rw2, rb2, rw3, rb3);
    {
        dim3 gq(16, BB);
        k_qt<<<gq, 128>>>(i1q, i1k, i2q, i2k);
    }
    {
        dim3 gr(2, BB);
        k_rc<<<gr, 128>>>(solution, ew1, eb1);
    }
    {
        dim3 gt(NT2B, BB);
        k_t2<<<gt, 256>>>(mt, ew2, eb2, ew3, eb3);
    }
    k_red<<<1, 64>>>(out);
}

// round 7
// speedup vs baseline: 18.6705x; 1.1173x over previous
#include <cuda_runtime.h>

#define BB 64
#define N1 201
#define DD 128
#define HF 100
#define MM (BB*N1)          // 12864
#define NEGV -1e20f
#define NT2B 101            // t2 blocks per batch (ceil(201/2))

typedef unsigned long long ull;

// ---------------- scratch ----------------
__device__ __align__(16) float g_gv[BB*DD];
__device__ __align__(16) float g_hhat[MM*DD];        // 6.6 MB
__device__ __align__(16) float g_M[4*DD*DD];         // WQ_h @ WK_h^T (removal)
__device__ __align__(16) float g_proj[4*MM*DD];      // P = hhat @ M_h (26 MB)
__device__ __align__(16) float g_qt[16*BB*DD];       // folded qtilde vectors
__device__ __align__(16) float g_rc[MM*32];
__device__ __align__(16) float g_cc[MM*32];
__device__ int   g_a1[BB];
__device__ float g_ll1[BB];
__device__ ull   g_pkey[BB*NT2B];
__device__ float g_psum[BB*NT2B];

// ---------------- f32x2 helpers ----------------
__device__ __forceinline__ ull ffma2(ull a, ull b, ull c) {
    ull d;
    asm("fma.rn.f32x2 %0, %1, %2, %3;" : "=l"(d) : "l"(a), "l"(b), "l"(c));
    return d;
}
__device__ __forceinline__ ull pack2(float x) {
    ull r;
    asm("mov.b64 %0, {%1, %2};" : "=l"(r) : "f"(x), "f"(x));
    return r;
}
__device__ __forceinline__ ull pack2v(float lo, float hi) {
    ull r;
    asm("mov.b64 %0, {%1, %2};" : "=l"(r) : "f"(lo), "f"(hi));
    return r;
}
__device__ __forceinline__ void unpack2(ull v, float& lo, float& hi) {
    asm("mov.b64 {%0, %1}, %2;" : "=f"(lo), "=f"(hi) : "l"(v));
}

// ---------------- K1: merged prep (blocks 0..63) + mmat (blocks 64..575) ----------------
__global__ __launch_bounds__(128) void k_prep_mmat(const float* __restrict__ hw,
                                                   const float* __restrict__ Wg,
                                                   const float* __restrict__ WQ,
                                                   const float* __restrict__ WK) {
    int bid = blockIdx.x;
    int tid = threadIdx.x;
    if (bid < BB) {
        __shared__ float hm[DD];
        int b = bid;
        const float* p = hw + (size_t)b*N1*DD + tid;
        float m = -3.4e38f;
        for (int n = 0; n < N1; n++) m = fmaxf(m, p[n*DD]);
        hm[tid] = m;
        __syncthreads();
        float s = 0.f;
        for (int k = 0; k < DD; k++) s += hm[k] * Wg[k*DD + tid];
        g_gv[b*DD + tid] = s;
    } else {
        __shared__ float wk[DD];
        int x = bid - BB;
        int h = x >> 7, dp = x & 127;
        wk[tid] = WK[(size_t)(h*DD + dp)*DD + tid];
        __syncthreads();
        const float4* q4 = (const float4*)(WQ + (size_t)(h*DD + tid)*DD);
        const float4* k4 = (const float4*)wk;
        float s = 0.f;
        #pragma unroll
        for (int c = 0; c < 32; c++) {
            float4 a = q4[c], bq = k4[c];
            s += a.x*bq.x + a.y*bq.y + a.z*bq.z + a.w*bq.w;
        }
        g_M[(size_t)(h*DD + tid)*DD + dp] = s;
    }
}

// ---------------- K2: h_hat = h_wave @ Wn + g[b] — f32x2, 16 rows/block ----------------
__global__ __launch_bounds__(128) void k_hhat(const float* __restrict__ hw,
                                              const float* __restrict__ Wn) {
    __shared__ float Asf[DD][18];   // [k][pair*2 + half], pad 18 for banks
    int r0 = blockIdx.x * 16;
    int tid = threadIdx.x;
    #pragma unroll
    for (int rr = 0; rr < 16; rr++) {
        Asf[tid][(rr & 7)*2 + (rr >> 3)] = hw[(size_t)(r0+rr)*DD + tid];
    }
    __syncthreads();
    ull acc[8];
    #pragma unroll
    for (int p = 0; p < 8; p++) {
        int bl = (r0 + p) / N1, bh = (r0 + p + 8) / N1;
        acc[p] = pack2v(g_gv[bl*DD + tid], g_gv[bh*DD + tid]);
    }
    #pragma unroll 4
    for (int k = 0; k < DD; k++) {
        ull w2 = pack2(Wn[k*DD + tid]);
        const ull* arow = (const ull*)&Asf[k][0];
        #pragma unroll
        for (int p = 0; p < 8; p++) acc[p] = ffma2(arow[p], w2, acc[p]);
    }
    #pragma unroll
    for (int p = 0; p < 8; p++) {
        float lo, hi; unpack2(acc[p], lo, hi);
        g_hhat[(size_t)(r0+p)*DD + tid]   = lo;
        g_hhat[(size_t)(r0+p+8)*DD + tid] = hi;
    }
}

// ---------------- K4: P = hhat @ M — f32x2 GEMM, 96x64 tile, 128 threads ----------------
__global__ __launch_bounds__(128) void k_pgemm() {
    __shared__ __align__(16) float As[16][98];   // pad 98: conflict-free STS/LDS
    __shared__ __align__(16) float Bs[16][64];
    int bm = blockIdx.x;              // 0..133 (134*96 = 12864 exact)
    int bn = blockIdx.y;              // 0..7
    int h  = bn >> 1;
    int d0 = (bn & 1) * 64;
    const float* W = g_M + (size_t)h * DD * DD;

    int tid = threadIdx.x;
    int tx = tid & 15, ty = tid >> 4;              // tx: n-group (4 cols), ty: m-group (12 rows)
    int brow = tid >> 3, bc0 = (tid & 7) * 8;
    ull c2[6][4] = {};

    for (int k0 = 0; k0 < DD; k0 += 16) {
        #pragma unroll
        for (int q = 0; q < 3; q++) {
            int idx = tid + 128*q;                 // 0..383
            int row = idx >> 2, c4 = (idx & 3) * 4;
            float4 a = *(const float4*)(g_hhat + (size_t)(bm*96 + row)*DD + k0 + c4);
            As[c4+0][row] = a.x; As[c4+1][row] = a.y;
            As[c4+2][row] = a.z; As[c4+3][row] = a.w;
        }
        *(float4*)&Bs[brow][bc0]   = *(const float4*)(W + (size_t)(k0+brow)*DD + d0 + bc0);
        *(float4*)&Bs[brow][bc0+4] = *(const float4*)(W + (size_t)(k0+brow)*DD + d0 + bc0 + 4);
        __syncthreads();
        #pragma unroll
        for (int kk = 0; kk < 16; kk++) {
            const ull* ap = (const ull*)&As[kk][ty*12];
            float4 bv = *(const float4*)&Bs[kk][tx*4];
            ull b0 = pack2(bv.x), b1 = pack2(bv.y), b2 = pack2(bv.z), b3 = pack2(bv.w);
            #pragma unroll
            for (int p = 0; p < 6; p++) {
                ull a2 = ap[p];
                c2[p][0] = ffma2(a2, b0, c2[p][0]);
                c2[p][1] = ffma2(a2, b1, c2[p][1]);
                c2[p][2] = ffma2(a2, b2, c2[p][2]);
                c2[p][3] = ffma2(a2, b3, c2[p][3]);
            }
        }
        __syncthreads();
    }
    float* out = g_proj + (size_t)h * MM * DD;
    int row0 = bm*96 + ty*12, col0 = d0 + tx*4;
    #pragma unroll
    for (int p = 0; p < 6; p++) {
        float l0,h0,l1,h1,l2,h2,l3,h3;
        unpack2(c2[p][0], l0, h0); unpack2(c2[p][1], l1, h1);
        unpack2(c2[p][2], l2, h2); unpack2(c2[p][3], l3, h3);
        float4 v0; v0.x=l0; v0.y=l1; v0.z=l2; v0.w=l3;
        float4 v1; v1.x=h0; v1.y=h1; v1.z=h2; v1.w=h3;
        *(float4*)(out + (size_t)(row0 + 2*p + 0)*DD + col0) = v0;
        *(float4*)(out + (size_t)(row0 + 2*p + 1)*DD + col0) = v1;
    }
}

// ---------------- K5: removal — warp-cooperative compat + MLP (512 threads) ----------------
__global__ __launch_bounds__(512) void k_t1(const int* __restrict__ sol_g,
                     const float* __restrict__ selrec,
                     const int* __restrict__ pre_action,
                     const float* __restrict__ w1, const float* __restrict__ b1,
                     const float* __restrict__ w2, const float* __restrict__ b2,
                     const float* __restrict__ w3, const float* __restrict__ b3) {
    __shared__ int sol[N1], inv[N1];
    __shared__ float feat_sh[HF][13];
    __shared__ float t1s[HF];
    __shared__ float W1[12*32], B1[32], W2s[32*32], B2s[32], W3s[32];
    int b = blockIdx.x, tid = threadIdx.x;
    int wid = tid >> 5, lane = tid & 31;
    for (int i = tid; i < N1; i += 512) sol[i] = sol_g[b*N1 + i];
    for (int i = tid; i < 12*32; i += 512) W1[i] = w1[i];
    for (int i = tid; i < 32*32; i += 512) W2s[i] = w2[i];
    if (tid < 32) { B1[tid] = b1[tid]; B2s[tid] = b2[tid]; W3s[tid] = w3[tid]; }
    __syncthreads();
    for (int i = tid; i < N1; i += 512) inv[sol[i]] = i;
    __syncthreads();

    for (int item = wid; item < 200; item += 16) {
        int n = item + 1;
        int half = (item < HF) ? 0 : 1;
        int m = (item < HF) ? item : (item - HF);
        int ipre  = inv[n];
        int ipost = sol[sol[n]];
        float4 xn = ((const float4*)(g_hhat + (size_t)(b*N1 + n    )*DD))[lane];
        float4 xp = ((const float4*)(g_hhat + (size_t)(b*N1 + ipost)*DD))[lane];
        #pragma unroll
        for (int h = 0; h < 4; h++) {
            float4 pp = ((const float4*)(g_proj + ((size_t)h*MM + b*N1 + ipre)*DD))[lane];
            float4 pn = ((const float4*)(g_proj + ((size_t)h*MM + b*N1 + n   )*DD))[lane];
            float s = pp.x*xn.x + pp.y*xn.y + pp.z*xn.z + pp.w*xn.w
                    + pn.x*xp.x + pn.y*xp.y + pn.z*xp.z + pn.w*xp.w
                    - (pp.x*xp.x + pp.y*xp.y + pp.z*xp.z + pp.w*xp.w);
            #pragma unroll
            for (int off = 16; off > 0; off >>= 1) s += __shfl_xor_sync(0xFFFFFFFF, s, off);
            if (lane == 0) feat_sh[m][half*4 + h] = s;
        }
    }
    for (int l = tid; l < 4*HF; l += 512) {
        int s = l / HF, m = l % HF;
        feat_sh[m][8 + s] = selrec[b*4*HF + l];
    }
    __syncthreads();

    if (tid < HF) {
        int m = tid;
        float h1[32];
        #pragma unroll
        for (int c = 0; c < 32; c++) {
            float s = B1[c];
            #pragma unroll
            for (int f = 0; f < 12; f++) s += feat_sh[m][f] * W1[f*32 + c];
            h1[c] = fmaxf(s, 0.f);
        }
        float h2[32];
        #pragma unroll
        for (int c = 0; c < 32; c++) {
            float s = B2s[c];
            #pragma unroll
            for (int f = 0; f < 32; f++) s += h1[f] * W2s[f*32 + c];
            h2[c] = fmaxf(s, 0.f);
        }
        float o = b3[0];
        #pragma unroll
        for (int c = 0; c < 32; c++) o += h2[c] * W3s[c];
        float t1 = tanhf(o) * 6.0f;
        if (pre_action[0] > 0 && m == pre_action[b*2]) t1 = NEGV;
        t1s[m] = t1;
    }
    __syncthreads();
    if (tid == 0) {
        float mx = t1s[0]; int am = 0;
        for (int m = 1; m < HF; m++) if (t1s[m] > mx) { mx = t1s[m]; am = m; }
        float se = 0.f;
        for (int m = 0; m < HF; m++) se += expf(t1s[m] - mx);
        g_a1[b] = am;
        g_ll1[b] = -logf(se);
    }
}

// ---------------- K6: qtilde = Wk @ (Wq^T h_sel) (16 per batch) ----------------
__global__ void k_qt(const float* __restrict__ i1q, const float* __restrict__ i1k,
                     const float* __restrict__ i2q, const float* __restrict__ i2k) {
    __shared__ float hp[DD];
    __shared__ float u[DD];
    __shared__ float Ws[DD*33];
    int x = blockIdx.x;               // t*4+h
    int t = x >> 2, h = x & 3;
    int b = blockIdx.y;
    int tid = threadIdx.x;
    int a1 = g_a1[b];
    int pos = (t < 2) ? (1 + a1) : (1 + HF + a1);
    hp[tid] = g_hhat[(size_t)(b*N1 + pos)*DD + tid];
    __syncthreads();
    const float* Wq = ((t & 1) ? i2q : i1q) + (size_t)h*DD*DD;
    const float* Wk = ((t & 1) ? i2k : i1k) + (size_t)h*DD*DD;
    float su = 0.f;
    for (int k = 0; k < DD; k++) su += hp[k] * Wq[k*DD + tid];
    u[tid] = su;
    __syncthreads();
    float acc = 0.f;
    for (int e0 = 0; e0 < DD; e0 += 32) {
        for (int l = tid; l < DD*32; l += 128) {
            int dd = l >> 5, ee = l & 31;
            Ws[dd*33 + ee] = Wk[(size_t)dd*DD + e0 + ee];
        }
        __syncthreads();
        const float* wr = Ws + tid*33;
        #pragma unroll
        for (int ee = 0; ee < 32; ee++) acc += u[e0+ee] * wr[ee];
        __syncthreads();
    }
    g_qt[((size_t)x*BB + b)*DD + tid] = acc;
}

// ---------------- K7: row/col layer-1 contributions ----------------
__global__ void k_rc(const int* __restrict__ sol_g,
                     const float* __restrict__ w1, const float* __restrict__ b1v) {
    __shared__ __align__(16) float qv[16*DD];
    __shared__ float W1[16*32], B1[32];
    int b = blockIdx.y;
    int tid = threadIdx.x;
    int i = blockIdx.x * 128 + tid;
    {
        const float4* src = (const float4*)(g_qt);
        float4* dst = (float4*)qv;
        for (int l = tid; l < 16*DD/4; l += 128) {
            int x = l >> 5, q = l & 31;     // 32 float4 per x-vector
            dst[l] = src[((size_t)x*BB + b)*32 + q];
        }
    }
    for (int l = tid; l < 16*32; l += 128) W1[l] = w1[l];
    if (tid < 32) B1[tid] = b1v[tid];
    __syncthreads();
    if (i < N1) {
        const float invs = 0.08838834764831845f;  // 1/sqrt(128)
        int si = sol_g[b*N1 + i];
        const float4* hi4 = (const float4*)(g_hhat + (size_t)(b*N1 + i )*DD);
        const float4* hs4 = (const float4*)(g_hhat + (size_t)(b*N1 + si)*DD);
        float s[16] = {};
        for (int c = 0; c < 32; c++) {
            float4 xi = hi4[c], xs = hs4[c];
            #pragma unroll
            for (int h = 0; h < 4; h++) {
                float4 q0 = ((const float4*)(qv + (0*4+h)*DD))[c];
                float4 q1 = ((const float4*)(qv + (1*4+h)*DD))[c];
                float4 q2 = ((const float4*)(qv + (2*4+h)*DD))[c];
                float4 q3 = ((const float4*)(qv + (3*4+h)*DD))[c];
                s[h]    += q0.x*xi.x + q0.y*xi.y + q0.z*xi.z + q0.w*xi.w;
                s[4+h]  += q1.x*xs.x + q1.y*xs.y + q1.z*xs.z + q1.w*xs.w;
                s[8+h]  += q2.x*xi.x + q2.y*xi.y + q2.z*xi.z + q2.w*xi.w;
                s[12+h] += q3.x*xs.x + q3.y*xs.y + q3.z*xs.z + q3.w*xs.w;
            }
        }
        #pragma unroll
        for (int c = 0; c < 32; c++) {
            float rs = 0.f, cs = B1[c];
            #pragma unroll
            for (int f = 0; f < 8; f++) {
                rs += s[f]*invs   * W1[f*32 + c];
                cs += s[8+f]*invs * W1[(8+f)*32 + c];
            }
            g_rc[(size_t)(b*N1 + i)*32 + c] = rs;
            g_cc[(size_t)(b*N1 + i)*32 + c] = cs;
        }
    }
}

// ---------------- K8: fused reinsertion MLP + in-block reduction — f32x2, kk-outer ----------------
__global__ __launch_bounds__(256, 1) void k_t2(const unsigned char* __restrict__ maskt,
                                               const float* __restrict__ w2, const float* __restrict__ b2,
                                               const float* __restrict__ w3, const float* __restrict__ b3) {
    __shared__ __align__(16) float W2[32*32];
    __shared__ __align__(8)  float B2[32];
    __shared__ float W3[32];
    __shared__ float rc0[32], rc1[32];
    __shared__ float cjs[N1*33];
    __shared__ ull   skw[8];
    __shared__ float ssw[8];
    __shared__ float B3;
    int b = blockIdx.y;
    int i0 = blockIdx.x * 2;
    int tid = threadIdx.x;
    int wid = tid >> 5, lane = tid & 31;
    for (int l = tid; l < 256; l += 256) {
        float4 v = ((const float4*)w2)[l];
        int kk = l >> 3, q = l & 7;
        W2[kk*32 + q*4 + 0] = v.x; W2[kk*32 + q*4 + 1] = v.y;
        W2[kk*32 + q*4 + 2] = v.z; W2[kk*32 + q*4 + 3] = v.w;
    }
    if (tid < 32) { B2[tid] = b2[tid]; W3[tid] = w3[tid]; }
    if (tid == 0) B3 = b3[0];
    if (tid < 32)      rc0[tid]    = g_rc[(size_t)(b*N1 + i0)*32 + tid];
    else if (tid < 64) rc1[tid-32] = (i0+1 < N1) ? g_rc[(size_t)(b*N1 + i0 + 1)*32 + (tid-32)] : 0.f;
    {
        const float4* ccb = (const float4*)(g_cc + (size_t)b*N1*32);
        for (int l = tid; l < N1*8; l += 256) {
            int j = l >> 3, q = l & 7;
            float4 v = ccb[l];
            cjs[j*33 + q*4 + 0] = v.x; cjs[j*33 + q*4 + 1] = v.y;
            cjs[j*33 + q*4 + 2] = v.z; cjs[j*33 + q*4 + 3] = v.w;
        }
    }
    __syncthreads();

    ull bk = 0; float bs = 0.f;
    int j = tid;
    if (j < N1) {
        const ull* B2d = (const ull*)B2;
        const float* cj = cjs + j*33;
        ull acc0[16], acc1[16];
        #pragma unroll
        for (int q = 0; q < 16; q++) { acc0[q] = B2d[q]; acc1[q] = B2d[q]; }
        #pragma unroll 4
        for (int kk = 0; kk < 32; kk++) {
            float cjk = cj[kk];
            ull hh0 = pack2(fmaxf(rc0[kk] + cjk, 0.f));
            ull hh1 = pack2(fmaxf(rc1[kk] + cjk, 0.f));
            const ulonglong2* wr = (const ulonglong2*)(W2 + kk*32);
            #pragma unroll
            for (int q = 0; q < 8; q++) {
                ulonglong2 w = wr[q];
                acc0[2*q]   = ffma2(hh0, w.x, acc0[2*q]);
                acc0[2*q+1] = ffma2(hh0, w.y, acc0[2*q+1]);
                acc1[2*q]   = ffma2(hh1, w.x, acc1[2*q]);
                acc1[2*q+1] = ffma2(hh1, w.y, acc1[2*q+1]);
            }
        }
        // epilogue row i0
        {
            int i = i0;
            float o = B3;
            #pragma unroll
            for (int q = 0; q < 16; q++) {
                float lo, hi;
                unpack2(acc0[q], lo, hi);
                o += fmaxf(lo, 0.f) * W3[2*q] + fmaxf(hi, 0.f) * W3[2*q+1];
            }
            float t2v = maskt[((size_t)b*N1 + i)*N1 + j] ? NEGV : tanhf(o)*6.0f;
            unsigned int lin = (unsigned int)(i*N1 + j);
            unsigned int u = __float_as_uint(t2v);
            unsigned int ord = (u >> 31) ? ~u : (u | 0x80000000u);
            ull key = ((ull)ord << 32) | (0xFFFFFFFFu - lin);
            if (key > bk) bk = key;
            bs += expf(t2v - 6.f);
        }
        // epilogue row i0+1
        if (i0 + 1 < N1) {
            int i = i0 + 1;
            float o = B3;
            #pragma unroll
            for (int q = 0; q < 16; q++) {
                float lo, hi;
                unpack2(acc1[q], lo, hi);
                o += fmaxf(lo, 0.f) * W3[2*q] + fmaxf(hi, 0.f) * W3[2*q+1];
            }
            float t2v = maskt[((size_t)b*N1 + i)*N1 + j] ? NEGV : tanhf(o)*6.0f;
            unsigned int lin = (unsigned int)(i*N1 + j);
            unsigned int u = __float_as_uint(t2v);
            unsigned int ord = (u >> 31) ? ~u : (u | 0x80000000u);
            ull key = ((ull)ord << 32) | (0xFFFFFFFFu - lin);
            if (key > bk) bk = key;
            bs += expf(t2v - 6.f);
        }
    }
    #pragma unroll
    for (int off = 16; off > 0; off >>= 1) {
        ull ok = __shfl_xor_sync(0xFFFFFFFF, bk, off);
        float os = __shfl_xor_sync(0xFFFFFFFF, bs, off);
        if (ok > bk) bk = ok;
        bs += os;
    }
    if (lane == 0) { skw[wid] = bk; ssw[wid] = bs; }
    __syncthreads();
    if (tid == 0) {
        ull k = skw[0]; float s = ssw[0];
        #pragma unroll
        for (int w = 1; w < 8; w++) {
            if (skw[w] > k) k = skw[w];
            s += ssw[w];
        }
        g_pkey[b*NT2B + blockIdx.x] = k;
        g_psum[b*NT2B + blockIdx.x] = s;
    }
}

// ---------------- K9: final per-batch reduce (deterministic) ----------------
__global__ void k_red(float* __restrict__ out) {
    int b = threadIdx.x;
    if (b < BB) {
        ull bk = 0; float s = 0.f;
        for (int p = 0; p < NT2B; p++) {
            ull k = g_pkey[b*NT2B + p];
            if (k > bk) bk = k;
            s += g_psum[b*NT2B + p];
        }
        unsigned int ord = (unsigned int)(bk >> 32);
        unsigned int u = (ord & 0x80000000u) ? (ord ^ 0x80000000u) : ~ord;
        float vmax = __uint_as_float(u);
        unsigned int lin = 0xFFFFFFFFu - (unsigned int)(bk & 0xFFFFFFFFu);
        float ll2 = vmax - 6.f - logf(s);
        out[b*3 + 0] = (float)g_a1[b];
        out[b*3 + 1] = (float)(lin / N1);
        out[b*3 + 2] = (float)(lin % N1);
        out[BB*3 + b] = g_ll1[b] + ll2;
    }
}

// ---------------- launch ----------------
extern "C" void kernel_launch(void* const* d_in, const int* in_sizes, int n_in,
                              void* d_out, int out_size) {
    const float* h_wave      = (const float*)d_in[0];
    const int*   solution    = (const int*)d_in[1];
    const float* selrec      = (const float*)d_in[2];
    const int*   pre_action  = (const int*)d_in[3];
    const unsigned char* mt  = (const unsigned char*)d_in[4];
    const float* Wn  = (const float*)d_in[5];
    const float* Wg  = (const float*)d_in[6];
    const float* rmWQ = (const float*)d_in[7];
    const float* rmWK = (const float*)d_in[8];
    const float* rw1 = (const float*)d_in[9];
    const float* rb1 = (const float*)d_in[10];
    const float* rw2 = (const float*)d_in[11];
    const float* rb2 = (const float*)d_in[12];
    const float* rw3 = (const float*)d_in[13];
    const float* rb3 = (const float*)d_in[14];
    const float* i1q = (const float*)d_in[15];
    const float* i1k = (const float*)d_in[16];
    const float* i2q = (const float*)d_in[17];
    const float* i2k = (const float*)d_in[18];
    const float* ew1 = (const float*)d_in[19];
    const float* eb1 = (const float*)d_in[20];
    const float* ew2 = (const float*)d_in[21];
    const float* eb2 = (const float*)d_in[22];
    const float* ew3 = (const float*)d_in[23];
    const float* eb3 = (const float*)d_in[24];
    float* out = (float*)d_out;

    k_prep_mmat<<<BB + 4*DD, DD>>>(h_wave, Wg, rmWQ, rmWK);
    k_hhat<<<MM/16, DD>>>(h_wave, Wn);
    {
        dim3 gg(134, 8);
        k_pgemm<<<gg, 128>>>();
    }
    k_t1<<<BB, 512>>>(solution, selrec, pre_action, rw1, rb1, rw2, rb2, rw3, rb3);
    {
        dim3 gq(16, BB);
        k_qt<<<gq, 128>>>(i1q, i1k, i2q, i2k);
    }
    {
        dim3 gr(2, BB);
        k_rc<<<gr, 128>>>(solution, ew1, eb1);
    }
    {
        dim3 gt(NT2B, BB);
        k_t2<<<gt, 256>>>(mt, ew2, eb2, ew3, eb3);
    }
    k_red<<<1, 64>>>(out);
}